// round 1
// baseline (speedup 1.0000x reference)
#include <cuda_runtime.h>
#include <math.h>

#define NB 32
#define ND 256
#define NRES 64
#define NTOK 4096
#define NSLOT 8
#define AST 264   // padded smem row stride for 256-wide tiles

// ---------------- scratch (device globals; no allocation allowed) ----------------
__device__ float g_k[NB * NTOK * ND];          // 134 MB
__device__ float g_v[NB * NTOK * ND];          // 134 MB
__device__ float g_stats_part[NB * 64 * 2];
__device__ float g_stats[NB * 2];              // mean, rstd per batch
__device__ float g_slots[NB * NSLOT * ND];
__device__ float g_q[NB * NSLOT * ND];
__device__ float g_upd_part[NB * 32 * NSLOT * ND];
__device__ float g_psum_part[NB * 32 * NSLOT];
__device__ float g_upd[NB * NSLOT * ND];

__device__ __forceinline__ float warp_sum(float v) {
#pragma unroll
    for (int o = 16; o; o >>= 1) v += __shfl_xor_sync(0xffffffffu, v, o);
    return v;
}

// ---------------- K0: per-batch sum / sumsq of h = x + pos ----------------
__global__ void __launch_bounds__(256) k_stats(const float* __restrict__ x,
                                               const float* __restrict__ pos_w,
                                               const float* __restrict__ pos_b) {
    int b = blockIdx.x, c = blockIdx.y, tid = threadIdx.x;
    float s = 0.f, q = 0.f;
    int base = c * 16384;
    for (int e = base + tid; e < base + 16384; e += 256) {
        int d = e >> 12;
        int ij = e & 4095;
        int ti = ij >> 6, tj = ij & 63;
        float fi = ti * (1.0f / 63.0f), fj = tj * (1.0f / 63.0f);
        float p = fi * pos_w[d] + fj * pos_w[256 + d] + (1.0f - fi) * pos_w[512 + d] +
                  (1.0f - fj) * pos_w[768 + d] + pos_b[d];
        float v = x[b * 1048576 + e] + p;
        s += v;
        q += v * v;
    }
    s = warp_sum(s);
    q = warp_sum(q);
    __shared__ float rs[8], rq[8];
    int w = tid >> 5, lane = tid & 31;
    if (lane == 0) { rs[w] = s; rq[w] = q; }
    __syncthreads();
    if (tid == 0) {
        float S = 0.f, Q = 0.f;
#pragma unroll
        for (int i = 0; i < 8; i++) { S += rs[i]; Q += rq[i]; }
        g_stats_part[(b * 64 + c) * 2 + 0] = S;
        g_stats_part[(b * 64 + c) * 2 + 1] = Q;
    }
}

__global__ void k_stats2() {
    int b = threadIdx.x;
    if (b < NB) {
        double S = 0.0, Q = 0.0;
        for (int c = 0; c < 64; c++) {
            S += (double)g_stats_part[(b * 64 + c) * 2 + 0];
            Q += (double)g_stats_part[(b * 64 + c) * 2 + 1];
        }
        double N = 1048576.0;
        double mu = S / N;
        double var = Q / N - mu * mu;
        g_stats[b * 2 + 0] = (float)mu;
        g_stats[b * 2 + 1] = (float)(1.0 / sqrt(var + 1e-5));
    }
}

// ---------------- tiled 32x256 @ 256x256 GEMM helper (smem src) ----------------
__device__ __forceinline__ void tile_gemm(const float* __restrict__ src,
                                          const float* __restrict__ W, float* Ws,
                                          float acc[4][8], int r0, int c0, int tid) {
#pragma unroll
    for (int i = 0; i < 4; i++)
#pragma unroll
        for (int j = 0; j < 8; j++) acc[i][j] = 0.f;
    for (int kc = 0; kc < 8; kc++) {
#pragma unroll 4
        for (int mm = 0; mm < 32; mm++) Ws[mm * 256 + tid] = W[(kc * 32 + mm) * 256 + tid];
        __syncthreads();
#pragma unroll
        for (int k = 0; k < 32; k++) {
            float a0 = src[(r0 + 0) * AST + kc * 32 + k];
            float a1 = src[(r0 + 1) * AST + kc * 32 + k];
            float a2 = src[(r0 + 2) * AST + kc * 32 + k];
            float a3 = src[(r0 + 3) * AST + kc * 32 + k];
            const float4 w0 = *(const float4*)&Ws[k * 256 + c0];
            const float4 w1 = *(const float4*)&Ws[k * 256 + c0 + 4];
            float wv[8] = {w0.x, w0.y, w0.z, w0.w, w1.x, w1.y, w1.z, w1.w};
#pragma unroll
            for (int j = 0; j < 8; j++) {
                acc[0][j] += a0 * wv[j];
                acc[1][j] += a1 * wv[j];
                acc[2][j] += a2 * wv[j];
                acc[3][j] += a3 * wv[j];
            }
        }
        __syncthreads();
    }
}

// ---------------- K1: fused encoder (pos + globalLN + MLP + LN + k/v proj) ----------------
__global__ void __launch_bounds__(256, 2) k_encoder(
    const float* __restrict__ x, const float* __restrict__ pos_w,
    const float* __restrict__ pos_b, const float* __restrict__ enc_g,
    const float* __restrict__ enc_b, const float* __restrict__ fm_w1,
    const float* __restrict__ fm_b1, const float* __restrict__ fm_w2,
    const float* __restrict__ fm_b2, const float* __restrict__ in_g,
    const float* __restrict__ in_b, const float* __restrict__ k_w,
    const float* __restrict__ k_b, const float* __restrict__ v_w,
    const float* __restrict__ v_b) {
    extern __shared__ float sm[];
    float* A  = sm;                  // 32*AST
    float* Bs = A + 32 * AST;        // 32*AST
    float* Ws = Bs + 32 * AST;       // 8192
    float* pw = Ws + 8192;           // 1024
    float* pb = pw + 1024;           // 256
    int b = blockIdx.y;
    int t0 = blockIdx.x * 32;
    int tid = threadIdx.x;

    for (int i = tid; i < 1024; i += 256) pw[i] = pos_w[i];
    pb[tid] = pos_b[tid];
    float mean = g_stats[b * 2 + 0], rstd = g_stats[b * 2 + 1];
    __syncthreads();

    // load x + pos (coalesced over tokens)
    {
        int tl = tid & 31, dg = tid >> 5;
        int t = t0 + tl;
        int ti = t >> 6, tj = t & 63;
        float fi = ti * (1.0f / 63.0f), fj = tj * (1.0f / 63.0f);
#pragma unroll 4
        for (int m = 0; m < 32; m++) {
            int d = m * 8 + dg;
            float p = fi * pw[d] + fj * pw[256 + d] + (1.0f - fi) * pw[512 + d] +
                      (1.0f - fj) * pw[768 + d] + pb[d];
            A[tl * AST + d] = x[(b * 256 + d) * 4096 + t] + p;
        }
    }
    __syncthreads();
    // global LN * enc_g + enc_b (coalesced over d)
    for (int m = 0; m < 32; m++) {
        int t = t0 + m;
        float v = A[m * AST + tid];
        A[m * AST + tid] = (v - mean) * rstd * enc_g[t * 256 + tid] + enc_b[t * 256 + tid];
    }
    __syncthreads();

    int rg = tid >> 5, cg = tid & 31;
    int r0 = rg * 4, c0 = cg * 8;
    float acc[4][8];

    // GEMM1 + relu  (A -> Bs)
    tile_gemm(A, fm_w1, Ws, acc, r0, c0, tid);
#pragma unroll
    for (int i = 0; i < 4; i++)
#pragma unroll
        for (int j = 0; j < 8; j++)
            Bs[(r0 + i) * AST + c0 + j] = fmaxf(acc[i][j] + fm_b1[c0 + j], 0.f);

    // GEMM2 + relu  (Bs -> A)
    tile_gemm(Bs, fm_w2, Ws, acc, r0, c0, tid);
#pragma unroll
    for (int i = 0; i < 4; i++)
#pragma unroll
        for (int j = 0; j < 8; j++)
            A[(r0 + i) * AST + c0 + j] = fmaxf(acc[i][j] + fm_b2[c0 + j], 0.f);
    __syncthreads();

    // LayerNorm over D per token (warp w -> tokens 4w..4w+3)
    {
        int w = tid >> 5, lane = tid & 31;
        for (int tk = 0; tk < 4; tk++) {
            int row = w * 4 + tk;
            float vv[8];
            float s1 = 0.f, s2 = 0.f;
#pragma unroll
            for (int u = 0; u < 8; u++) {
                vv[u] = A[row * AST + lane + 32 * u];
                s1 += vv[u];
                s2 += vv[u] * vv[u];
            }
            s1 = warp_sum(s1);
            s2 = warp_sum(s2);
            float mu = s1 * (1.0f / 256.0f);
            float rsd = rsqrtf(s2 * (1.0f / 256.0f) - mu * mu + 1e-5f);
#pragma unroll
            for (int u = 0; u < 8; u++) {
                int d = lane + 32 * u;
                A[row * AST + d] = (vv[u] - mu) * rsd * in_g[d] + in_b[d];
            }
        }
    }
    __syncthreads();

    // k projection (A -> g_k)
    tile_gemm(A, k_w, Ws, acc, r0, c0, tid);
#pragma unroll
    for (int i = 0; i < 4; i++) {
        int t = t0 + r0 + i;
        float* dst = g_k + (b * 4096 + t) * 256 + c0;
#pragma unroll
        for (int j = 0; j < 8; j++) dst[j] = acc[i][j] + k_b[c0 + j];
    }
    // v projection (A -> g_v)
    tile_gemm(A, v_w, Ws, acc, r0, c0, tid);
#pragma unroll
    for (int i = 0; i < 4; i++) {
        int t = t0 + r0 + i;
        float* dst = g_v + (b * 4096 + t) * 256 + c0;
#pragma unroll
        for (int j = 0; j < 8; j++) dst[j] = acc[i][j] + v_b[c0 + j];
    }
}

// ---------------- slot init ----------------
__global__ void k_init(const float* __restrict__ eps, const float* __restrict__ loc,
                       const float* __restrict__ lsc) {
    int b = blockIdx.x, tid = threadIdx.x;
    for (int idx = tid; idx < 2048; idx += 256) {
        int d = idx & 255;
        g_slots[b * 2048 + idx] = loc[d] + __expf(lsc[d]) * eps[b * 2048 + idx];
    }
}

// ---------------- per-iter: slot LN + q projection (scaled) ----------------
__global__ void __launch_bounds__(256) k_q(const float* __restrict__ q_w,
                                           const float* __restrict__ q_b,
                                           const float* __restrict__ slot_g,
                                           const float* __restrict__ slot_b) {
    __shared__ float ss[8 * 256];
    int b = blockIdx.x, tid = threadIdx.x, w = tid >> 5, lane = tid & 31;
    {
        float vv[8];
        float s1 = 0.f, s2 = 0.f;
#pragma unroll
        for (int u = 0; u < 8; u++) {
            vv[u] = g_slots[(b * 8 + w) * 256 + lane + 32 * u];
            s1 += vv[u];
            s2 += vv[u] * vv[u];
        }
        s1 = warp_sum(s1);
        s2 = warp_sum(s2);
        float mu = s1 * (1.0f / 256.0f);
        float rsd = rsqrtf(s2 * (1.0f / 256.0f) - mu * mu + 1e-5f);
#pragma unroll
        for (int u = 0; u < 8; u++) {
            int d = lane + 32 * u;
            ss[w * 256 + d] = (vv[u] - mu) * rsd * slot_g[d] + slot_b[d];
        }
    }
    __syncthreads();
    float acc[8];
#pragma unroll
    for (int i = 0; i < 8; i++) acc[i] = 0.f;
    for (int k = 0; k < 256; k++) {
        float wv = q_w[k * 256 + tid];
#pragma unroll
        for (int i = 0; i < 8; i++) acc[i] += ss[i * 256 + k] * wv;
    }
    float qb = q_b[tid];
#pragma unroll
    for (int i = 0; i < 8; i++)
        g_q[(b * 8 + i) * 256 + tid] = (acc[i] + qb) * 0.0625f;  // * D^-0.5
}

// ---------------- per-iter: streaming attention (softmax over slots) ----------------
__global__ void __launch_bounds__(256) k_attn() {
    extern __shared__ float sm[];
    float* qs = sm;             // 2048
    float* red = qs + 2048;     // 8 * 2048
    float* psum_s = red + 16384;// 64
    int tile = blockIdx.x, b = blockIdx.y;
    int tid = threadIdx.x, w = tid >> 5, lane = tid & 31;
    for (int i = tid; i < 2048; i += 256) qs[i] = g_q[b * 2048 + i];
    __syncthreads();
    float av[8][8];
    float ps[8];
#pragma unroll
    for (int i = 0; i < 8; i++) {
        ps[i] = 0.f;
#pragma unroll
        for (int j = 0; j < 8; j++) av[i][j] = 0.f;
    }
    int tbase = tile * 128 + w * 16;
    for (int n = 0; n < 16; n++) {
        int t = tbase + n;
        const float4* kp = (const float4*)(g_k + ((size_t)(b * 4096 + t)) * 256);
        float4 k0 = kp[lane * 2], k1 = kp[lane * 2 + 1];
        float e[8];
        float m = -1e30f;
#pragma unroll
        for (int i = 0; i < 8; i++) {
            const float4* qp = (const float4*)(qs + i * 256);
            float4 q0 = qp[lane * 2], q1 = qp[lane * 2 + 1];
            float p = k0.x * q0.x + k0.y * q0.y + k0.z * q0.z + k0.w * q0.w +
                      k1.x * q1.x + k1.y * q1.y + k1.z * q1.z + k1.w * q1.w;
            p = warp_sum(p);
            e[i] = p;
            m = fmaxf(m, p);
        }
        float tot = 0.f;
#pragma unroll
        for (int i = 0; i < 8; i++) {
            e[i] = __expf(e[i] - m);
            tot += e[i];
        }
        float inv = 1.f / tot;
        const float4* vp = (const float4*)(g_v + ((size_t)(b * 4096 + t)) * 256);
        float4 v0 = vp[lane * 2], v1 = vp[lane * 2 + 1];
#pragma unroll
        for (int i = 0; i < 8; i++) {
            float p = e[i] * inv + 1e-8f;
            ps[i] += p;
            av[i][0] += p * v0.x; av[i][1] += p * v0.y;
            av[i][2] += p * v0.z; av[i][3] += p * v0.w;
            av[i][4] += p * v1.x; av[i][5] += p * v1.y;
            av[i][6] += p * v1.z; av[i][7] += p * v1.w;
        }
    }
#pragma unroll
    for (int i = 0; i < 8; i++)
#pragma unroll
        for (int j = 0; j < 8; j++) red[w * 2048 + i * 256 + lane * 8 + j] = av[i][j];
    if (lane == 0) {
#pragma unroll
        for (int i = 0; i < 8; i++) psum_s[w * 8 + i] = ps[i];
    }
    __syncthreads();
    for (int uu = 0; uu < 8; uu++) {
        int idx = uu * 256 + tid;
        float ssum = 0.f;
#pragma unroll
        for (int ww = 0; ww < 8; ww++) ssum += red[ww * 2048 + idx];
        g_upd_part[((size_t)(b * 32 + tile)) * 2048 + idx] = ssum;
    }
    if (tid < 8) {
        float ssum = 0.f;
#pragma unroll
        for (int ww = 0; ww < 8; ww++) ssum += psum_s[ww * 8 + tid];
        g_psum_part[(b * 32 + tile) * 8 + tid] = ssum;
    }
}

// ---------------- per-iter: finalize upd (deterministic fixed-order reduce) ----------------
__global__ void __launch_bounds__(256) k_upd() {
    int b = blockIdx.x, tid = threadIdx.x;
    __shared__ float ps[8];
    if (tid < 8) {
        float s = 0.f;
        for (int tl = 0; tl < 32; tl++) s += g_psum_part[(b * 32 + tl) * 8 + tid];
        ps[tid] = s;
    }
    __syncthreads();
#pragma unroll
    for (int i = 0; i < 8; i++) {
        float s = 0.f;
        for (int tl = 0; tl < 32; tl++)
            s += g_upd_part[((size_t)(b * 32 + tl)) * 2048 + i * 256 + tid];
        g_upd[b * 2048 + i * 256 + tid] = s / ps[i];
    }
}

// ---------------- per-iter: GRU + residual slot MLP ----------------
__global__ void __launch_bounds__(256) k_gru(
    const float* __restrict__ wih, const float* __restrict__ whh,
    const float* __restrict__ bih, const float* __restrict__ bhh,
    const float* __restrict__ pre_g, const float* __restrict__ pre_b,
    const float* __restrict__ w1, const float* __restrict__ b1,
    const float* __restrict__ w2, const float* __restrict__ b2) {
    extern __shared__ float sm[];
    float* u = sm;           // 2048
    float* pv = u + 2048;    // 2048
    float* gi = pv + 2048;   // 6144
    float* gh = gi + 6144;   // 6144
    float* hn = gh + 6144;   // 2048
    float* ff = hn + 2048;   // 2048
    int b = blockIdx.x, tid = threadIdx.x;
    for (int idx = tid; idx < 2048; idx += 256) {
        u[idx] = g_upd[b * 2048 + idx];
        pv[idx] = g_slots[b * 2048 + idx];
    }
    __syncthreads();
    for (int cc = 0; cc < 3; cc++) {
        int c = cc * 256 + tid;
        float aI[8], aH[8];
        float bi = bih[c], bh = bhh[c];
#pragma unroll
        for (int s = 0; s < 8; s++) { aI[s] = bi; aH[s] = bh; }
        for (int k = 0; k < 256; k++) {
            float wi = wih[k * 768 + c], wh = whh[k * 768 + c];
#pragma unroll
            for (int s = 0; s < 8; s++) {
                aI[s] += u[s * 256 + k] * wi;
                aH[s] += pv[s * 256 + k] * wh;
            }
        }
#pragma unroll
        for (int s = 0; s < 8; s++) { gi[s * 768 + c] = aI[s]; gh[s * 768 + c] = aH[s]; }
    }
    __syncthreads();
#pragma unroll
    for (int s = 0; s < 8; s++) {
        float r = 1.f / (1.f + __expf(-(gi[s * 768 + tid] + gh[s * 768 + tid])));
        float z = 1.f / (1.f + __expf(-(gi[s * 768 + 256 + tid] + gh[s * 768 + 256 + tid])));
        float n = tanhf(gi[s * 768 + 512 + tid] + r * gh[s * 768 + 512 + tid]);
        hn[s * 256 + tid] = (1.f - z) * n + z * pv[s * 256 + tid];
    }
    __syncthreads();
    {
        int w = tid >> 5, lane = tid & 31;
        float vv[8];
        float s1 = 0.f, s2 = 0.f;
#pragma unroll
        for (int uu = 0; uu < 8; uu++) {
            vv[uu] = hn[w * 256 + lane + 32 * uu];
            s1 += vv[uu];
            s2 += vv[uu] * vv[uu];
        }
        s1 = warp_sum(s1);
        s2 = warp_sum(s2);
        float mu = s1 * (1.0f / 256.0f);
        float rsd = rsqrtf(s2 * (1.0f / 256.0f) - mu * mu + 1e-5f);
#pragma unroll
        for (int uu = 0; uu < 8; uu++) {
            int d = lane + 32 * uu;
            ff[w * 256 + d] = (vv[uu] - mu) * rsd * pre_g[d] + pre_b[d];
        }
    }
    __syncthreads();
    {
        float acc[8];
        float bb = b1[tid];
#pragma unroll
        for (int s = 0; s < 8; s++) acc[s] = bb;
        for (int k = 0; k < 256; k++) {
            float wv = w1[k * 256 + tid];
#pragma unroll
            for (int s = 0; s < 8; s++) acc[s] += ff[s * 256 + k] * wv;
        }
#pragma unroll
        for (int s = 0; s < 8; s++) gi[s * 256 + tid] = fmaxf(acc[s], 0.f);
    }
    __syncthreads();
    {
        float acc[8];
        float bb = b2[tid];
#pragma unroll
        for (int s = 0; s < 8; s++) acc[s] = bb;
        for (int k = 0; k < 256; k++) {
            float wv = w2[k * 256 + tid];
#pragma unroll
            for (int s = 0; s < 8; s++) acc[s] += gi[s * 256 + k] * wv;
        }
#pragma unroll
        for (int s = 0; s < 8; s++)
            g_slots[b * 2048 + s * 256 + tid] = hn[s * 256 + tid] + fmaxf(acc[s], 0.f);
    }
}

__global__ void k_copy(float* __restrict__ out) {
    int i = blockIdx.x * 256 + threadIdx.x;
    if (i < NB * NSLOT * ND) out[i] = g_slots[i];
}

// ---------------- host launcher ----------------
extern "C" void kernel_launch(void* const* d_in, const int* in_sizes, int n_in,
                              void* d_out, int out_size) {
    const float* x          = (const float*)d_in[0];
    const float* eps_noise  = (const float*)d_in[1];
    const float* pos_w      = (const float*)d_in[2];
    const float* pos_b      = (const float*)d_in[3];
    const float* enc_g      = (const float*)d_in[4];
    const float* enc_b      = (const float*)d_in[5];
    const float* fm_w1      = (const float*)d_in[6];
    const float* fm_b1      = (const float*)d_in[7];
    const float* fm_w2      = (const float*)d_in[8];
    const float* fm_b2      = (const float*)d_in[9];
    const float* in_g       = (const float*)d_in[10];
    const float* in_b       = (const float*)d_in[11];
    const float* q_w        = (const float*)d_in[12];
    const float* q_b        = (const float*)d_in[13];
    const float* k_w        = (const float*)d_in[14];
    const float* k_b        = (const float*)d_in[15];
    const float* v_w        = (const float*)d_in[16];
    const float* v_b        = (const float*)d_in[17];
    const float* gru_wih    = (const float*)d_in[18];
    const float* gru_whh    = (const float*)d_in[19];
    const float* gru_bih    = (const float*)d_in[20];
    const float* gru_bhh    = (const float*)d_in[21];
    const float* pre_g      = (const float*)d_in[22];
    const float* pre_b      = (const float*)d_in[23];
    const float* st_w1      = (const float*)d_in[24];
    const float* st_b1      = (const float*)d_in[25];
    const float* st_w2      = (const float*)d_in[26];
    const float* st_b2      = (const float*)d_in[27];
    const float* slot_g     = (const float*)d_in[28];
    const float* slot_b     = (const float*)d_in[29];
    const float* slots_loc  = (const float*)d_in[30];
    const float* slots_lsc  = (const float*)d_in[31];

    const int ENC_SMEM  = (32 * AST * 2 + 32 * 256 + 1024 + 256) * 4;  // 105472
    const int ATTN_SMEM = (2048 + 16384 + 64) * 4;                     // 73984
    const int GRU_SMEM  = 20480 * 4;                                   // 81920

    cudaFuncSetAttribute(k_encoder, cudaFuncAttributeMaxDynamicSharedMemorySize, ENC_SMEM);
    cudaFuncSetAttribute(k_attn, cudaFuncAttributeMaxDynamicSharedMemorySize, ATTN_SMEM);
    cudaFuncSetAttribute(k_gru, cudaFuncAttributeMaxDynamicSharedMemorySize, GRU_SMEM);

    k_stats<<<dim3(32, 64), 256>>>(x, pos_w, pos_b);
    k_stats2<<<1, 32>>>();
    k_encoder<<<dim3(128, 32), 256, ENC_SMEM>>>(x, pos_w, pos_b, enc_g, enc_b, fm_w1, fm_b1,
                                                fm_w2, fm_b2, in_g, in_b, k_w, k_b, v_w, v_b);
    k_init<<<32, 256>>>(eps_noise, slots_loc, slots_lsc);
    for (int it = 0; it < 3; it++) {
        k_q<<<32, 256>>>(q_w, q_b, slot_g, slot_b);
        k_attn<<<dim3(32, 32), 256, ATTN_SMEM>>>();
        k_upd<<<32, 256>>>();
        k_gru<<<32, 256, GRU_SMEM>>>(gru_wih, gru_whh, gru_bih, gru_bhh, pre_g, pre_b,
                                     st_w1, st_b1, st_w2, st_b2);
    }
    k_copy<<<256, 256>>>((float*)d_out);
}

// round 4
// speedup vs baseline: 2.0810x; 2.0810x over previous
#include <cuda_runtime.h>
#include <math.h>
#include <stdint.h>

#define NB 32
#define ND 256
#define NTOK 4096
#define NSLOT 8

// ---------------- scratch (device globals; no allocation allowed) ----------------
__device__ float g_k[NB * NTOK * ND];          // 134 MB
__device__ float g_v[NB * NTOK * ND];          // 134 MB
__device__ uint32_t g_wt[4][ND * ND];          // tf32 weights: w1, w2, k_w, v_w
__device__ float g_stats_part[NB * 64 * 2];
__device__ float g_stats[NB * 2];              // mean, rstd per batch
__device__ float g_slots[NB * NSLOT * ND];
__device__ float g_q[NB * NSLOT * ND];
__device__ float g_upd_part[NB * 32 * NSLOT * ND];
__device__ float g_psum_part[NB * 32 * NSLOT];
__device__ float g_upd[NB * NSLOT * ND];

__device__ __forceinline__ float warp_sum(float v) {
#pragma unroll
    for (int o = 16; o; o >>= 1) v += __shfl_xor_sync(0xffffffffu, v, o);
    return v;
}

__device__ __forceinline__ float f2tf32(float x) {
    uint32_t u;
    asm("cvt.rna.tf32.f32 %0, %1;" : "=r"(u) : "f"(x));
    return __uint_as_float(u);
}

// ---------------- K0: per-batch sum / sumsq of h = x + pos ----------------
__global__ void __launch_bounds__(256) k_stats(const float* __restrict__ x,
                                               const float* __restrict__ pos_w,
                                               const float* __restrict__ pos_b) {
    int b = blockIdx.x, c = blockIdx.y, tid = threadIdx.x;
    float s = 0.f, q = 0.f;
    int base = c * 16384;
    for (int e = base + tid; e < base + 16384; e += 256) {
        int d = e >> 12;
        int ij = e & 4095;
        int ti = ij >> 6, tj = ij & 63;
        float fi = ti * (1.0f / 63.0f), fj = tj * (1.0f / 63.0f);
        float p = fi * pos_w[d] + fj * pos_w[256 + d] + (1.0f - fi) * pos_w[512 + d] +
                  (1.0f - fj) * pos_w[768 + d] + pos_b[d];
        float v = x[b * 1048576 + e] + p;
        s += v;
        q += v * v;
    }
    s = warp_sum(s);
    q = warp_sum(q);
    __shared__ float rs[8], rq[8];
    int w = tid >> 5, lane = tid & 31;
    if (lane == 0) { rs[w] = s; rq[w] = q; }
    __syncthreads();
    if (tid == 0) {
        float S = 0.f, Q = 0.f;
#pragma unroll
        for (int i = 0; i < 8; i++) { S += rs[i]; Q += rq[i]; }
        g_stats_part[(b * 64 + c) * 2 + 0] = S;
        g_stats_part[(b * 64 + c) * 2 + 1] = Q;
    }
}

__global__ void k_stats2() {
    int b = threadIdx.x;
    if (b < NB) {
        double S = 0.0, Q = 0.0;
        for (int c = 0; c < 64; c++) {
            S += (double)g_stats_part[(b * 64 + c) * 2 + 0];
            Q += (double)g_stats_part[(b * 64 + c) * 2 + 1];
        }
        double N = 1048576.0;
        double mu = S / N;
        double var = Q / N - mu * mu;
        g_stats[b * 2 + 0] = (float)mu;
        g_stats[b * 2 + 1] = (float)(1.0 / sqrt(var + 1e-5));
    }
}

// ---------------- weight pre-conversion to tf32 ----------------
__global__ void __launch_bounds__(256) k_cvtW(const float* __restrict__ w1,
                                              const float* __restrict__ w2,
                                              const float* __restrict__ wk,
                                              const float* __restrict__ wv) {
    int i = blockIdx.x * 256 + threadIdx.x;
    g_wt[0][i] = __float_as_uint(f2tf32(w1[i]));
    g_wt[1][i] = __float_as_uint(f2tf32(w2[i]));
    g_wt[2][i] = __float_as_uint(f2tf32(wk[i]));
    g_wt[3][i] = __float_as_uint(f2tf32(wv[i]));
}

// ---------------- tf32 mma ----------------
__device__ __forceinline__ void mma8(float* c, const uint32_t a[4], uint32_t b0, uint32_t b1) {
    asm volatile(
        "mma.sync.aligned.m16n8k8.row.col.f32.tf32.tf32.f32 "
        "{%0,%1,%2,%3}, {%4,%5,%6,%7}, {%8,%9}, {%0,%1,%2,%3};"
        : "+f"(c[0]), "+f"(c[1]), "+f"(c[2]), "+f"(c[3])
        : "r"(a[0]), "r"(a[1]), "r"(a[2]), "r"(a[3]), "r"(b0), "r"(b1));
}

#define A_ST 260   // A smem row stride (floats): bank = 4g+t, conflict-free
#define W_ST 264   // W chunk smem row stride (floats): bank = 8t+g, conflict-free
#define A_FLOATS (128 * A_ST)
#define WBUF_FLOATS (2 * 16 * W_ST)

// Full 128x256x256 tf32 GEMM: A (smem, tf32-in-fp32) @ W (global tf32) -> acc
__device__ __forceinline__ void run_gemm(const uint32_t* __restrict__ Wg,
                                         const float* As, float* Wbuf,
                                         float acc[2][16][4], int wm, int wn,
                                         int lane, int tid) {
#pragma unroll
    for (int mt = 0; mt < 2; mt++)
#pragma unroll
        for (int nt = 0; nt < 16; nt++)
#pragma unroll
            for (int e = 0; e < 4; e++) acc[mt][nt][e] = 0.f;

    const uint32_t* Asu = (const uint32_t*)As;
    int g = lane >> 2, t = lane & 3;
    uint32_t wb_base = (uint32_t)__cvta_generic_to_shared(Wbuf);

    // prologue: stage chunk 0
    {
#pragma unroll
        for (int q = 0; q < 4; q++) {
            int v = tid + q * 256;
            int row = v >> 6, c4 = (v & 63) * 4;
            uint32_t dst = wb_base + (row * W_ST + c4) * 4;
            const uint32_t* src = Wg + row * 256 + c4;
            asm volatile("cp.async.cg.shared.global [%0], [%1], 16;" ::"r"(dst), "l"(src));
        }
        asm volatile("cp.async.commit_group;");
    }

#pragma unroll 2
    for (int kc = 0; kc < 16; kc++) {
        if (kc + 1 < 16) {
            int nb = (kc + 1) & 1;
#pragma unroll
            for (int q = 0; q < 4; q++) {
                int v = tid + q * 256;
                int row = v >> 6, c4 = (v & 63) * 4;
                uint32_t dst = wb_base + (nb * 16 * W_ST + row * W_ST + c4) * 4;
                const uint32_t* src = Wg + ((kc + 1) * 16 + row) * 256 + c4;
                asm volatile("cp.async.cg.shared.global [%0], [%1], 16;" ::"r"(dst), "l"(src));
            }
            asm volatile("cp.async.commit_group;");
            asm volatile("cp.async.wait_group 1;");
        } else {
            asm volatile("cp.async.wait_group 0;");
        }
        __syncthreads();
        const uint32_t* Wb = (const uint32_t*)(Wbuf + (kc & 1) * 16 * W_ST);
#pragma unroll
        for (int ck = 0; ck < 2; ck++) {
            int k0 = kc * 16 + ck * 8;  // global k for A
            int kk = ck * 8;            // local k within chunk
            uint32_t a[2][4];
#pragma unroll
            for (int mt = 0; mt < 2; mt++) {
                int r = wm * 32 + mt * 16 + g;
                a[mt][0] = Asu[r * A_ST + k0 + t];
                a[mt][1] = Asu[(r + 8) * A_ST + k0 + t];
                a[mt][2] = Asu[r * A_ST + k0 + t + 4];
                a[mt][3] = Asu[(r + 8) * A_ST + k0 + t + 4];
            }
#pragma unroll
            for (int nt = 0; nt < 16; nt++) {
                int c = wn * 128 + nt * 8 + g;
                uint32_t b0 = Wb[(kk + t) * W_ST + c];
                uint32_t b1 = Wb[(kk + t + 4) * W_ST + c];
                mma8(acc[0][nt], a[0], b0, b1);
                mma8(acc[1][nt], a[1], b0, b1);
            }
        }
        __syncthreads();
    }
}

// ---------------- K1: fused tensor-core encoder ----------------
__global__ void __launch_bounds__(256, 1) k_encoder(
    const float* __restrict__ x, const float* __restrict__ pos_w,
    const float* __restrict__ pos_b, const float* __restrict__ enc_g,
    const float* __restrict__ enc_b, const float* __restrict__ fm_b1,
    const float* __restrict__ fm_b2, const float* __restrict__ in_g,
    const float* __restrict__ in_b, const float* __restrict__ k_b,
    const float* __restrict__ v_b) {
    extern __shared__ float sm[];
    float* A = sm;                    // 128*260
    float* Wbuf = A + A_FLOATS;       // 2*16*264
    float* pw = Wbuf + WBUF_FLOATS;   // 1024
    float* pb = pw + 1024;            // 256

    int b = blockIdx.y;
    int t0 = blockIdx.x * 128;
    int tid = threadIdx.x;
    int wid = tid >> 5, lane = tid & 31;
    int wm = wid & 3, wn = wid >> 2;
    int g = lane >> 2, t = lane & 3;

    for (int i = tid; i < 1024; i += 256) pw[i] = pos_w[i];
    pb[tid] = pos_b[tid];
    float mean = g_stats[b * 2 + 0], rstd = g_stats[b * 2 + 1];
    __syncthreads();

    // load x + pos into A (coalesced over tokens)
    {
        int tl = tid & 31, dg = tid >> 5;
#pragma unroll
        for (int tk = 0; tk < 4; tk++) {
            int m = tk * 32 + tl;
            int tok = t0 + m;
            int ti = tok >> 6, tj = tok & 63;
            float fi = ti * (1.0f / 63.0f), fj = tj * (1.0f / 63.0f);
#pragma unroll 8
            for (int u = 0; u < 32; u++) {
                int d = u * 8 + dg;
                float p = fi * pw[d] + fj * pw[256 + d] + (1.0f - fi) * pw[512 + d] +
                          (1.0f - fj) * pw[768 + d] + pb[d];
                A[m * A_ST + d] = x[(b * 256 + d) * 4096 + tok] + p;
            }
        }
    }
    __syncthreads();
    // global LN * enc_g + enc_b, convert to tf32 (coalesced over d)
    for (int m = 0; m < 128; m++) {
        int tok = t0 + m;
        float v = A[m * A_ST + tid];
        A[m * A_ST + tid] =
            f2tf32((v - mean) * rstd * enc_g[tok * 256 + tid] + enc_b[tok * 256 + tid]);
    }
    __syncthreads();

    float acc[2][16][4];

    // GEMM1 + relu -> A (tf32)
    run_gemm(g_wt[0], A, Wbuf, acc, wm, wn, lane, tid);
#pragma unroll
    for (int nt = 0; nt < 16; nt++) {
        int c = wn * 128 + nt * 8 + 2 * t;
        float bb0 = fm_b1[c], bb1 = fm_b1[c + 1];
#pragma unroll
        for (int mt = 0; mt < 2; mt++) {
            int r = wm * 32 + mt * 16 + g;
            float* a = acc[mt][nt];
            A[r * A_ST + c] = f2tf32(fmaxf(a[0] + bb0, 0.f));
            A[r * A_ST + c + 1] = f2tf32(fmaxf(a[1] + bb1, 0.f));
            A[(r + 8) * A_ST + c] = f2tf32(fmaxf(a[2] + bb0, 0.f));
            A[(r + 8) * A_ST + c + 1] = f2tf32(fmaxf(a[3] + bb1, 0.f));
        }
    }
    __syncthreads();

    // GEMM2 + relu -> A (tf32)
    run_gemm(g_wt[1], A, Wbuf, acc, wm, wn, lane, tid);
#pragma unroll
    for (int nt = 0; nt < 16; nt++) {
        int c = wn * 128 + nt * 8 + 2 * t;
        float bb0 = fm_b2[c], bb1 = fm_b2[c + 1];
#pragma unroll
        for (int mt = 0; mt < 2; mt++) {
            int r = wm * 32 + mt * 16 + g;
            float* a = acc[mt][nt];
            A[r * A_ST + c] = f2tf32(fmaxf(a[0] + bb0, 0.f));
            A[r * A_ST + c + 1] = f2tf32(fmaxf(a[1] + bb1, 0.f));
            A[(r + 8) * A_ST + c] = f2tf32(fmaxf(a[2] + bb0, 0.f));
            A[(r + 8) * A_ST + c + 1] = f2tf32(fmaxf(a[3] + bb1, 0.f));
        }
    }
    __syncthreads();

    // per-token LayerNorm over D (16 rows per warp), write tf32
    for (int rr = 0; rr < 16; rr++) {
        int r = wid * 16 + rr;
        float vv[8];
        float s1 = 0.f, s2 = 0.f;
#pragma unroll
        for (int u = 0; u < 8; u++) {
            vv[u] = A[r * A_ST + lane + 32 * u];
            s1 += vv[u];
            s2 += vv[u] * vv[u];
        }
        s1 = warp_sum(s1);
        s2 = warp_sum(s2);
        float mu = s1 * (1.0f / 256.0f);
        float rsd = rsqrtf(s2 * (1.0f / 256.0f) - mu * mu + 1e-5f);
#pragma unroll
        for (int u = 0; u < 8; u++) {
            int d = lane + 32 * u;
            A[r * A_ST + d] = f2tf32((vv[u] - mu) * rsd * in_g[d] + in_b[d]);
        }
    }
    __syncthreads();

    // k projection -> g_k (fp32)
    run_gemm(g_wt[2], A, Wbuf, acc, wm, wn, lane, tid);
#pragma unroll
    for (int nt = 0; nt < 16; nt++) {
        int c = wn * 128 + nt * 8 + 2 * t;
        float bb0 = k_b[c], bb1 = k_b[c + 1];
#pragma unroll
        for (int mt = 0; mt < 2; mt++) {
            int r = wm * 32 + mt * 16 + g;
            float* a = acc[mt][nt];
            float2 v0 = make_float2(a[0] + bb0, a[1] + bb1);
            float2 v1 = make_float2(a[2] + bb0, a[3] + bb1);
            *(float2*)&g_k[((size_t)b * 4096 + t0 + r) * 256 + c] = v0;
            *(float2*)&g_k[((size_t)b * 4096 + t0 + r + 8) * 256 + c] = v1;
        }
    }

    // v projection -> g_v (fp32)
    run_gemm(g_wt[3], A, Wbuf, acc, wm, wn, lane, tid);
#pragma unroll
    for (int nt = 0; nt < 16; nt++) {
        int c = wn * 128 + nt * 8 + 2 * t;
        float bb0 = v_b[c], bb1 = v_b[c + 1];
#pragma unroll
        for (int mt = 0; mt < 2; mt++) {
            int r = wm * 32 + mt * 16 + g;
            float* a = acc[mt][nt];
            float2 v0 = make_float2(a[0] + bb0, a[1] + bb1);
            float2 v1 = make_float2(a[2] + bb0, a[3] + bb1);
            *(float2*)&g_v[((size_t)b * 4096 + t0 + r) * 256 + c] = v0;
            *(float2*)&g_v[((size_t)b * 4096 + t0 + r + 8) * 256 + c] = v1;
        }
    }
}

// ---------------- slot init ----------------
__global__ void k_init(const float* __restrict__ eps, const float* __restrict__ loc,
                       const float* __restrict__ lsc) {
    int b = blockIdx.x, tid = threadIdx.x;
    for (int idx = tid; idx < 2048; idx += 256) {
        int d = idx & 255;
        g_slots[b * 2048 + idx] = loc[d] + __expf(lsc[d]) * eps[b * 2048 + idx];
    }
}

// ---------------- per-iter: slot LN + q projection (scaled) ----------------
__global__ void __launch_bounds__(256) k_q(const float* __restrict__ q_w,
                                           const float* __restrict__ q_b,
                                           const float* __restrict__ slot_g,
                                           const float* __restrict__ slot_b) {
    __shared__ float ss[8 * 256];
    int b = blockIdx.x, tid = threadIdx.x, w = tid >> 5, lane = tid & 31;
    {
        float vv[8];
        float s1 = 0.f, s2 = 0.f;
#pragma unroll
        for (int u = 0; u < 8; u++) {
            vv[u] = g_slots[(b * 8 + w) * 256 + lane + 32 * u];
            s1 += vv[u];
            s2 += vv[u] * vv[u];
        }
        s1 = warp_sum(s1);
        s2 = warp_sum(s2);
        float mu = s1 * (1.0f / 256.0f);
        float rsd = rsqrtf(s2 * (1.0f / 256.0f) - mu * mu + 1e-5f);
#pragma unroll
        for (int u = 0; u < 8; u++) {
            int d = lane + 32 * u;
            ss[w * 256 + d] = (vv[u] - mu) * rsd * slot_g[d] + slot_b[d];
        }
    }
    __syncthreads();
    float acc[8];
#pragma unroll
    for (int i = 0; i < 8; i++) acc[i] = 0.f;
    for (int k = 0; k < 256; k++) {
        float wv = q_w[k * 256 + tid];
#pragma unroll
        for (int i = 0; i < 8; i++) acc[i] += ss[i * 256 + k] * wv;
    }
    float qb = q_b[tid];
#pragma unroll
    for (int i = 0; i < 8; i++)
        g_q[(b * 8 + i) * 256 + tid] = (acc[i] + qb) * 0.0625f;  // * D^-0.5
}

// ---------------- per-iter: streaming attention (softmax over slots) ----------------
__global__ void __launch_bounds__(256) k_attn() {
    extern __shared__ float sm[];
    float* qs = sm;              // 2048
    float* red = qs + 2048;      // 8 * 2048
    float* psum_s = red + 16384; // 64
    int tile = blockIdx.x, b = blockIdx.y;
    int tid = threadIdx.x, w = tid >> 5, lane = tid & 31;
    for (int i = tid; i < 2048; i += 256) qs[i] = g_q[b * 2048 + i];
    __syncthreads();
    float av[8][8];
    float ps[8];
#pragma unroll
    for (int i = 0; i < 8; i++) {
        ps[i] = 0.f;
#pragma unroll
        for (int j = 0; j < 8; j++) av[i][j] = 0.f;
    }
    int tbase = tile * 128 + w * 16;
    for (int n = 0; n < 16; n++) {
        int t = tbase + n;
        const float4* kp = (const float4*)(g_k + ((size_t)(b * 4096 + t)) * 256);
        float4 k0 = kp[lane * 2], k1 = kp[lane * 2 + 1];
        float e[8];
        float m = -1e30f;
#pragma unroll
        for (int i = 0; i < 8; i++) {
            const float4* qp = (const float4*)(qs + i * 256);
            float4 q0 = qp[lane * 2], q1 = qp[lane * 2 + 1];
            float p = k0.x * q0.x + k0.y * q0.y + k0.z * q0.z + k0.w * q0.w +
                      k1.x * q1.x + k1.y * q1.y + k1.z * q1.z + k1.w * q1.w;
            p = warp_sum(p);
            e[i] = p;
            m = fmaxf(m, p);
        }
        float tot = 0.f;
#pragma unroll
        for (int i = 0; i < 8; i++) {
            e[i] = __expf(e[i] - m);
            tot += e[i];
        }
        float inv = 1.f / tot;
        const float4* vp = (const float4*)(g_v + ((size_t)(b * 4096 + t)) * 256);
        float4 v0 = vp[lane * 2], v1 = vp[lane * 2 + 1];
#pragma unroll
        for (int i = 0; i < 8; i++) {
            float p = e[i] * inv + 1e-8f;
            ps[i] += p;
            av[i][0] += p * v0.x; av[i][1] += p * v0.y;
            av[i][2] += p * v0.z; av[i][3] += p * v0.w;
            av[i][4] += p * v1.x; av[i][5] += p * v1.y;
            av[i][6] += p * v1.z; av[i][7] += p * v1.w;
        }
    }
#pragma unroll
    for (int i = 0; i < 8; i++)
#pragma unroll
        for (int j = 0; j < 8; j++) red[w * 2048 + i * 256 + lane * 8 + j] = av[i][j];
    if (lane == 0) {
#pragma unroll
        for (int i = 0; i < 8; i++) psum_s[w * 8 + i] = ps[i];
    }
    __syncthreads();
    for (int uu = 0; uu < 8; uu++) {
        int idx = uu * 256 + tid;
        float ssum = 0.f;
#pragma unroll
        for (int ww = 0; ww < 8; ww++) ssum += red[ww * 2048 + idx];
        g_upd_part[((size_t)(b * 32 + tile)) * 2048 + idx] = ssum;
    }
    if (tid < 8) {
        float ssum = 0.f;
#pragma unroll
        for (int ww = 0; ww < 8; ww++) ssum += psum_s[ww * 8 + tid];
        g_psum_part[(b * 32 + tile) * 8 + tid] = ssum;
    }
}

// ---------------- per-iter: finalize upd (deterministic fixed-order reduce) ----------------
__global__ void __launch_bounds__(256) k_upd() {
    int b = blockIdx.x, tid = threadIdx.x;
    __shared__ float ps[8];
    if (tid < 8) {
        float s = 0.f;
        for (int tl = 0; tl < 32; tl++) s += g_psum_part[(b * 32 + tl) * 8 + tid];
        ps[tid] = s;
    }
    __syncthreads();
#pragma unroll
    for (int i = 0; i < 8; i++) {
        float s = 0.f;
        for (int tl = 0; tl < 32; tl++)
            s += g_upd_part[((size_t)(b * 32 + tl)) * 2048 + i * 256 + tid];
        g_upd[b * 2048 + i * 256 + tid] = s / ps[i];
    }
}

// ---------------- per-iter: GRU + residual slot MLP ----------------
__global__ void __launch_bounds__(256) k_gru(
    const float* __restrict__ wih, const float* __restrict__ whh,
    const float* __restrict__ bih, const float* __restrict__ bhh,
    const float* __restrict__ pre_g, const float* __restrict__ pre_b,
    const float* __restrict__ w1, const float* __restrict__ b1,
    const float* __restrict__ w2, const float* __restrict__ b2) {
    extern __shared__ float sm[];
    float* u = sm;           // 2048
    float* pv = u + 2048;    // 2048
    float* gi = pv + 2048;   // 6144
    float* gh = gi + 6144;   // 6144
    float* hn = gh + 6144;   // 2048
    float* ff = hn + 2048;   // 2048
    int b = blockIdx.x, tid = threadIdx.x;
    for (int idx = tid; idx < 2048; idx += 256) {
        u[idx] = g_upd[b * 2048 + idx];
        pv[idx] = g_slots[b * 2048 + idx];
    }
    __syncthreads();
    for (int cc = 0; cc < 3; cc++) {
        int c = cc * 256 + tid;
        float aI[8], aH[8];
        float bi = bih[c], bh = bhh[c];
#pragma unroll
        for (int s = 0; s < 8; s++) { aI[s] = bi; aH[s] = bh; }
        for (int k = 0; k < 256; k++) {
            float wi = wih[k * 768 + c], wh = whh[k * 768 + c];
#pragma unroll
            for (int s = 0; s < 8; s++) {
                aI[s] += u[s * 256 + k] * wi;
                aH[s] += pv[s * 256 + k] * wh;
            }
        }
#pragma unroll
        for (int s = 0; s < 8; s++) { gi[s * 768 + c] = aI[s]; gh[s * 768 + c] = aH[s]; }
    }
    __syncthreads();
#pragma unroll
    for (int s = 0; s < 8; s++) {
        float r = 1.f / (1.f + __expf(-(gi[s * 768 + tid] + gh[s * 768 + tid])));
        float z = 1.f / (1.f + __expf(-(gi[s * 768 + 256 + tid] + gh[s * 768 + 256 + tid])));
        float n = tanhf(gi[s * 768 + 512 + tid] + r * gh[s * 768 + 512 + tid]);
        hn[s * 256 + tid] = (1.f - z) * n + z * pv[s * 256 + tid];
    }
    __syncthreads();
    {
        int w = tid >> 5, lane = tid & 31;
        float vv[8];
        float s1 = 0.f, s2 = 0.f;
#pragma unroll
        for (int uu = 0; uu < 8; uu++) {
            vv[uu] = hn[w * 256 + lane + 32 * uu];
            s1 += vv[uu];
            s2 += vv[uu] * vv[uu];
        }
        s1 = warp_sum(s1);
        s2 = warp_sum(s2);
        float mu = s1 * (1.0f / 256.0f);
        float rsd = rsqrtf(s2 * (1.0f / 256.0f) - mu * mu + 1e-5f);
#pragma unroll
        for (int uu = 0; uu < 8; uu++) {
            int d = lane + 32 * uu;
            ff[w * 256 + d] = (vv[uu] - mu) * rsd * pre_g[d] + pre_b[d];
        }
    }
    __syncthreads();
    {
        float acc[8];
        float bb = b1[tid];
#pragma unroll
        for (int s = 0; s < 8; s++) acc[s] = bb;
        for (int k = 0; k < 256; k++) {
            float wv = w1[k * 256 + tid];
#pragma unroll
            for (int s = 0; s < 8; s++) acc[s] += ff[s * 256 + k] * wv;
        }
#pragma unroll
        for (int s = 0; s < 8; s++) gi[s * 256 + tid] = fmaxf(acc[s], 0.f);
    }
    __syncthreads();
    {
        float acc[8];
        float bb = b2[tid];
#pragma unroll
        for (int s = 0; s < 8; s++) acc[s] = bb;
        for (int k = 0; k < 256; k++) {
            float wv = w2[k * 256 + tid];
#pragma unroll
            for (int s = 0; s < 8; s++) acc[s] += gi[s * 256 + k] * wv;
        }
#pragma unroll
        for (int s = 0; s < 8; s++)
            g_slots[b * 2048 + s * 256 + tid] = hn[s * 256 + tid] + fmaxf(acc[s], 0.f);
    }
}

__global__ void k_copy(float* __restrict__ out) {
    int i = blockIdx.x * 256 + threadIdx.x;
    if (i < NB * NSLOT * ND) out[i] = g_slots[i];
}

// ---------------- host launcher ----------------
extern "C" void kernel_launch(void* const* d_in, const int* in_sizes, int n_in,
                              void* d_out, int out_size) {
    const float* x          = (const float*)d_in[0];
    const float* eps_noise  = (const float*)d_in[1];
    const float* pos_w      = (const float*)d_in[2];
    const float* pos_b      = (const float*)d_in[3];
    const float* enc_g      = (const float*)d_in[4];
    const float* enc_b      = (const float*)d_in[5];
    const float* fm_w1      = (const float*)d_in[6];
    const float* fm_b1      = (const float*)d_in[7];
    const float* fm_w2      = (const float*)d_in[8];
    const float* fm_b2      = (const float*)d_in[9];
    const float* in_g       = (const float*)d_in[10];
    const float* in_b       = (const float*)d_in[11];
    const float* q_w        = (const float*)d_in[12];
    const float* q_b        = (const float*)d_in[13];
    const float* k_w        = (const float*)d_in[14];
    const float* k_b        = (const float*)d_in[15];
    const float* v_w        = (const float*)d_in[16];
    const float* v_b        = (const float*)d_in[17];
    const float* gru_wih    = (const float*)d_in[18];
    const float* gru_whh    = (const float*)d_in[19];
    const float* gru_bih    = (const float*)d_in[20];
    const float* gru_bhh    = (const float*)d_in[21];
    const float* pre_g      = (const float*)d_in[22];
    const float* pre_b      = (const float*)d_in[23];
    const float* st_w1      = (const float*)d_in[24];
    const float* st_b1      = (const float*)d_in[25];
    const float* st_w2      = (const float*)d_in[26];
    const float* st_b2      = (const float*)d_in[27];
    const float* slot_g     = (const float*)d_in[28];
    const float* slot_b     = (const float*)d_in[29];
    const float* slots_loc  = (const float*)d_in[30];
    const float* slots_lsc  = (const float*)d_in[31];

    const int ENC_SMEM  = (A_FLOATS + WBUF_FLOATS + 1024 + 256) * 4;  // 172032
    const int ATTN_SMEM = (2048 + 16384 + 64) * 4;                    // 73984
    const int GRU_SMEM  = 20480 * 4;                                  // 81920

    cudaFuncSetAttribute(k_encoder, cudaFuncAttributeMaxDynamicSharedMemorySize, ENC_SMEM);
    cudaFuncSetAttribute(k_attn, cudaFuncAttributeMaxDynamicSharedMemorySize, ATTN_SMEM);
    cudaFuncSetAttribute(k_gru, cudaFuncAttributeMaxDynamicSharedMemorySize, GRU_SMEM);

    k_stats<<<dim3(32, 64), 256>>>(x, pos_w, pos_b);
    k_cvtW<<<256, 256>>>(fm_w1, fm_w2, k_w, v_w);
    k_stats2<<<1, 32>>>();
    k_encoder<<<dim3(32, 32), 256, ENC_SMEM>>>(x, pos_w, pos_b, enc_g, enc_b, fm_b1, fm_b2,
                                               in_g, in_b, k_b, v_b);
    k_init<<<32, 256>>>(eps_noise, slots_loc, slots_lsc);
    for (int it = 0; it < 3; it++) {
        k_q<<<32, 256>>>(q_w, q_b, slot_g, slot_b);
        k_attn<<<dim3(32, 32), 256, ATTN_SMEM>>>();
        k_upd<<<32, 256>>>();
        k_gru<<<32, 256, GRU_SMEM>>>(gru_wih, gru_whh, gru_bih, gru_bhh, pre_g, pre_b,
                                     st_w1, st_b1, st_w2, st_b2);
    }
    k_copy<<<256, 256>>>((float*)d_out);
}

// round 6
// speedup vs baseline: 2.5386x; 1.2199x over previous
#include <cuda_runtime.h>
#include <math.h>
#include <stdint.h>

#define NB 32
#define ND 256
#define NTOK 4096
#define NSLOT 8

// ---------------- scratch (device globals; no allocation allowed) ----------------
__device__ float g_k[NB * NTOK * ND];          // 134 MB
__device__ float g_v[NB * NTOK * ND];          // 134 MB
__device__ uint32_t g_wt[4][ND * ND];          // tf32 weights: w1, w2, k_w, v_w
__device__ float g_stats_part[NB * 64 * 2];
__device__ float g_stats[NB * 2];              // mean, rstd per batch
__device__ float g_slots[NB * NSLOT * ND];
__device__ float g_q[NB * NSLOT * ND];
__device__ float g_upd_part[NB * 32 * NSLOT * ND];
__device__ float g_psum_part[NB * 32 * NSLOT];
__device__ float g_upd[NB * NSLOT * ND];
__device__ float g_gi[NB * NSLOT * 768];
__device__ float g_gh[NB * NSLOT * 768];

__device__ __forceinline__ float warp_sum(float v) {
#pragma unroll
    for (int o = 16; o; o >>= 1) v += __shfl_xor_sync(0xffffffffu, v, o);
    return v;
}

__device__ __forceinline__ float f2tf32(float x) {
    uint32_t u;
    asm("cvt.rna.tf32.f32 %0, %1;" : "=r"(u) : "f"(x));
    return __uint_as_float(u);
}

// ---------------- K0: per-batch sum / sumsq of h = x + pos ----------------
__global__ void __launch_bounds__(256) k_stats(const float* __restrict__ x,
                                               const float* __restrict__ pos_w,
                                               const float* __restrict__ pos_b) {
    int b = blockIdx.x, c = blockIdx.y, tid = threadIdx.x;
    float s = 0.f, q = 0.f;
    int base = c * 16384;
    for (int e = base + tid; e < base + 16384; e += 256) {
        int d = e >> 12;
        int ij = e & 4095;
        int ti = ij >> 6, tj = ij & 63;
        float fi = ti * (1.0f / 63.0f), fj = tj * (1.0f / 63.0f);
        float p = fi * pos_w[d] + fj * pos_w[256 + d] + (1.0f - fi) * pos_w[512 + d] +
                  (1.0f - fj) * pos_w[768 + d] + pos_b[d];
        float v = x[b * 1048576 + e] + p;
        s += v;
        q += v * v;
    }
    s = warp_sum(s);
    q = warp_sum(q);
    __shared__ float rs[8], rq[8];
    int w = tid >> 5, lane = tid & 31;
    if (lane == 0) { rs[w] = s; rq[w] = q; }
    __syncthreads();
    if (tid == 0) {
        float S = 0.f, Q = 0.f;
#pragma unroll
        for (int i = 0; i < 8; i++) { S += rs[i]; Q += rq[i]; }
        g_stats_part[(b * 64 + c) * 2 + 0] = S;
        g_stats_part[(b * 64 + c) * 2 + 1] = Q;
    }
}

__global__ void k_stats2() {
    int b = threadIdx.x;
    if (b < NB) {
        double S = 0.0, Q = 0.0;
        for (int c = 0; c < 64; c++) {
            S += (double)g_stats_part[(b * 64 + c) * 2 + 0];
            Q += (double)g_stats_part[(b * 64 + c) * 2 + 1];
        }
        double N = 1048576.0;
        double mu = S / N;
        double var = Q / N - mu * mu;
        g_stats[b * 2 + 0] = (float)mu;
        g_stats[b * 2 + 1] = (float)(1.0 / sqrt(var + 1e-5));
    }
}

// ---------------- weight pre-conversion to tf32 ----------------
__global__ void __launch_bounds__(256) k_cvtW(const float* __restrict__ w1,
                                              const float* __restrict__ w2,
                                              const float* __restrict__ wk,
                                              const float* __restrict__ wv) {
    int i = blockIdx.x * 256 + threadIdx.x;
    g_wt[0][i] = __float_as_uint(f2tf32(w1[i]));
    g_wt[1][i] = __float_as_uint(f2tf32(w2[i]));
    g_wt[2][i] = __float_as_uint(f2tf32(wk[i]));
    g_wt[3][i] = __float_as_uint(f2tf32(wv[i]));
}

// ---------------- tf32 mma ----------------
__device__ __forceinline__ void mma8(float* c, const uint32_t a[4], uint32_t b0, uint32_t b1) {
    asm volatile(
        "mma.sync.aligned.m16n8k8.row.col.f32.tf32.tf32.f32 "
        "{%0,%1,%2,%3}, {%4,%5,%6,%7}, {%8,%9}, {%0,%1,%2,%3};"
        : "+f"(c[0]), "+f"(c[1]), "+f"(c[2]), "+f"(c[3])
        : "r"(a[0]), "r"(a[1]), "r"(a[2]), "r"(a[3]), "r"(b0), "r"(b1));
}

#define A_ST 260   // A smem row stride (floats)
#define W_ST 264   // W chunk smem row stride (floats)
#define A_FLOATS (128 * A_ST)
#define WBUF_FLOATS (4 * 16 * W_ST)   // 4-stage pipeline

// Full 128x256x256 tf32 GEMM: A (smem) @ W (global tf32) -> acc. 4-stage cp.async.
__device__ __forceinline__ void run_gemm(const uint32_t* __restrict__ Wg,
                                         const float* As, float* Wbuf,
                                         float acc[2][16][4], int wm, int wn,
                                         int lane, int tid) {
#pragma unroll
    for (int mt = 0; mt < 2; mt++)
#pragma unroll
        for (int nt = 0; nt < 16; nt++)
#pragma unroll
            for (int e = 0; e < 4; e++) acc[mt][nt][e] = 0.f;

    const uint32_t* Asu = (const uint32_t*)As;
    int g = lane >> 2, t = lane & 3;
    uint32_t wb_base = (uint32_t)__cvta_generic_to_shared(Wbuf);

    auto stage = [&](int kc) {
        int st = kc & 3;
#pragma unroll
        for (int q2 = 0; q2 < 4; q2++) {
            int v = tid + q2 * 256;
            int row = v >> 6, c4 = (v & 63) * 4;
            uint32_t dst = wb_base + (uint32_t)(((st * 16 + row) * W_ST + c4) * 4);
            const uint32_t* src = Wg + (kc * 16 + row) * 256 + c4;
            asm volatile("cp.async.cg.shared.global [%0], [%1], 16;" ::"r"(dst), "l"(src));
        }
        asm volatile("cp.async.commit_group;");
    };
    stage(0);
    stage(1);
    stage(2);

#pragma unroll 2
    for (int kc = 0; kc < 16; kc++) {
        asm volatile("cp.async.wait_group 2;");
        __syncthreads();
        if (kc + 3 < 16) stage(kc + 3);
        else asm volatile("cp.async.commit_group;");
        const uint32_t* Wb = (const uint32_t*)(Wbuf + (kc & 3) * 16 * W_ST);
#pragma unroll
        for (int ck = 0; ck < 2; ck++) {
            int k0 = kc * 16 + ck * 8;
            int kk = ck * 8;
            uint32_t a[2][4];
#pragma unroll
            for (int mt = 0; mt < 2; mt++) {
                int r = wm * 32 + mt * 16 + g;
                a[mt][0] = Asu[r * A_ST + k0 + t];
                a[mt][1] = Asu[(r + 8) * A_ST + k0 + t];
                a[mt][2] = Asu[r * A_ST + k0 + t + 4];
                a[mt][3] = Asu[(r + 8) * A_ST + k0 + t + 4];
            }
#pragma unroll
            for (int nt = 0; nt < 16; nt++) {
                int c = wn * 128 + nt * 8 + g;
                uint32_t b0 = Wb[(kk + t) * W_ST + c];
                uint32_t b1 = Wb[(kk + t + 4) * W_ST + c];
                mma8(acc[0][nt], a[0], b0, b1);
                mma8(acc[1][nt], a[1], b0, b1);
            }
        }
    }
    __syncthreads();
}

// ---------------- K1: fused tensor-core encoder ----------------
__global__ void __launch_bounds__(256, 1) k_encoder(
    const float* __restrict__ x, const float* __restrict__ pos_w,
    const float* __restrict__ pos_b, const float* __restrict__ enc_g,
    const float* __restrict__ enc_b, const float* __restrict__ fm_b1,
    const float* __restrict__ fm_b2, const float* __restrict__ in_g,
    const float* __restrict__ in_b, const float* __restrict__ k_b,
    const float* __restrict__ v_b) {
    extern __shared__ float sm[];
    float* A = sm;                    // 128*260
    float* Wbuf = A + A_FLOATS;       // 4*16*264
    float* pw = Wbuf + WBUF_FLOATS;   // 1024
    float* pb = pw + 1024;            // 256

    int b = blockIdx.y;
    int t0 = blockIdx.x * 128;
    int tid = threadIdx.x;
    int wid = tid >> 5, lane = tid & 31;
    int wm = wid & 3, wn = wid >> 2;
    int g = lane >> 2, t = lane & 3;

    for (int i = tid; i < 1024; i += 256) pw[i] = pos_w[i];
    pb[tid] = pos_b[tid];
    float mean = g_stats[b * 2 + 0], rstd = g_stats[b * 2 + 1];
    __syncthreads();

    // load x + pos into A (coalesced over tokens)
    {
        int tl = tid & 31, dg = tid >> 5;
#pragma unroll
        for (int tk = 0; tk < 4; tk++) {
            int m = tk * 32 + tl;
            int tok = t0 + m;
            int ti = tok >> 6, tj = tok & 63;
            float fi = ti * (1.0f / 63.0f), fj = tj * (1.0f / 63.0f);
#pragma unroll 8
            for (int u = 0; u < 32; u++) {
                int d = u * 8 + dg;
                float p = fi * pw[d] + fj * pw[256 + d] + (1.0f - fi) * pw[512 + d] +
                          (1.0f - fj) * pw[768 + d] + pb[d];
                A[m * A_ST + d] = x[(b * 256 + d) * 4096 + tok] + p;
            }
        }
    }
    __syncthreads();
    // global LN * enc_g + enc_b, convert to tf32
    for (int m = 0; m < 128; m++) {
        int tok = t0 + m;
        float v = A[m * A_ST + tid];
        A[m * A_ST + tid] =
            f2tf32((v - mean) * rstd * enc_g[tok * 256 + tid] + enc_b[tok * 256 + tid]);
    }
    __syncthreads();

    float acc[2][16][4];

    // GEMM1 + relu -> A
    run_gemm(g_wt[0], A, Wbuf, acc, wm, wn, lane, tid);
#pragma unroll
    for (int nt = 0; nt < 16; nt++) {
        int c = wn * 128 + nt * 8 + 2 * t;
        float bb0 = fm_b1[c], bb1 = fm_b1[c + 1];
#pragma unroll
        for (int mt = 0; mt < 2; mt++) {
            int r = wm * 32 + mt * 16 + g;
            float* a = acc[mt][nt];
            A[r * A_ST + c] = f2tf32(fmaxf(a[0] + bb0, 0.f));
            A[r * A_ST + c + 1] = f2tf32(fmaxf(a[1] + bb1, 0.f));
            A[(r + 8) * A_ST + c] = f2tf32(fmaxf(a[2] + bb0, 0.f));
            A[(r + 8) * A_ST + c + 1] = f2tf32(fmaxf(a[3] + bb1, 0.f));
        }
    }
    __syncthreads();

    // GEMM2 + relu -> A
    run_gemm(g_wt[1], A, Wbuf, acc, wm, wn, lane, tid);
#pragma unroll
    for (int nt = 0; nt < 16; nt++) {
        int c = wn * 128 + nt * 8 + 2 * t;
        float bb0 = fm_b2[c], bb1 = fm_b2[c + 1];
#pragma unroll
        for (int mt = 0; mt < 2; mt++) {
            int r = wm * 32 + mt * 16 + g;
            float* a = acc[mt][nt];
            A[r * A_ST + c] = f2tf32(fmaxf(a[0] + bb0, 0.f));
            A[r * A_ST + c + 1] = f2tf32(fmaxf(a[1] + bb1, 0.f));
            A[(r + 8) * A_ST + c] = f2tf32(fmaxf(a[2] + bb0, 0.f));
            A[(r + 8) * A_ST + c + 1] = f2tf32(fmaxf(a[3] + bb1, 0.f));
        }
    }
    __syncthreads();

    // per-token LayerNorm over D
    for (int rr = 0; rr < 16; rr++) {
        int r = wid * 16 + rr;
        float vv[8];
        float s1 = 0.f, s2 = 0.f;
#pragma unroll
        for (int u = 0; u < 8; u++) {
            vv[u] = A[r * A_ST + lane + 32 * u];
            s1 += vv[u];
            s2 += vv[u] * vv[u];
        }
        s1 = warp_sum(s1);
        s2 = warp_sum(s2);
        float mu = s1 * (1.0f / 256.0f);
        float rsd = rsqrtf(s2 * (1.0f / 256.0f) - mu * mu + 1e-5f);
#pragma unroll
        for (int u = 0; u < 8; u++) {
            int d = lane + 32 * u;
            A[r * A_ST + d] = f2tf32((vv[u] - mu) * rsd * in_g[d] + in_b[d]);
        }
    }
    __syncthreads();

    // k projection -> g_k
    run_gemm(g_wt[2], A, Wbuf, acc, wm, wn, lane, tid);
#pragma unroll
    for (int nt = 0; nt < 16; nt++) {
        int c = wn * 128 + nt * 8 + 2 * t;
        float bb0 = k_b[c], bb1 = k_b[c + 1];
#pragma unroll
        for (int mt = 0; mt < 2; mt++) {
            int r = wm * 32 + mt * 16 + g;
            float* a = acc[mt][nt];
            *(float2*)&g_k[((size_t)b * 4096 + t0 + r) * 256 + c] =
                make_float2(a[0] + bb0, a[1] + bb1);
            *(float2*)&g_k[((size_t)b * 4096 + t0 + r + 8) * 256 + c] =
                make_float2(a[2] + bb0, a[3] + bb1);
        }
    }

    // v projection -> g_v
    run_gemm(g_wt[3], A, Wbuf, acc, wm, wn, lane, tid);
#pragma unroll
    for (int nt = 0; nt < 16; nt++) {
        int c = wn * 128 + nt * 8 + 2 * t;
        float bb0 = v_b[c], bb1 = v_b[c + 1];
#pragma unroll
        for (int mt = 0; mt < 2; mt++) {
            int r = wm * 32 + mt * 16 + g;
            float* a = acc[mt][nt];
            *(float2*)&g_v[((size_t)b * 4096 + t0 + r) * 256 + c] =
                make_float2(a[0] + bb0, a[1] + bb1);
            *(float2*)&g_v[((size_t)b * 4096 + t0 + r + 8) * 256 + c] =
                make_float2(a[2] + bb0, a[3] + bb1);
        }
    }
}

// ---------------- slot init ----------------
__global__ void k_init(const float* __restrict__ eps, const float* __restrict__ loc,
                       const float* __restrict__ lsc) {
    int b = blockIdx.x, tid = threadIdx.x;
    for (int idx = tid; idx < 2048; idx += 256) {
        int d = idx & 255;
        g_slots[b * 2048 + idx] = loc[d] + __expf(lsc[d]) * eps[b * 2048 + idx];
    }
}

// ---------------- per-iter: slot LN + q projection (scaled) ----------------
__global__ void __launch_bounds__(256) k_q(const float* __restrict__ q_w,
                                           const float* __restrict__ q_b,
                                           const float* __restrict__ slot_g,
                                           const float* __restrict__ slot_b) {
    __shared__ float ss[8 * 256];
    int b = blockIdx.x, tid = threadIdx.x, w = tid >> 5, lane = tid & 31;
    {
        float vv[8];
        float s1 = 0.f, s2 = 0.f;
#pragma unroll
        for (int u = 0; u < 8; u++) {
            vv[u] = g_slots[(b * 8 + w) * 256 + lane + 32 * u];
            s1 += vv[u];
            s2 += vv[u] * vv[u];
        }
        s1 = warp_sum(s1);
        s2 = warp_sum(s2);
        float mu = s1 * (1.0f / 256.0f);
        float rsd = rsqrtf(s2 * (1.0f / 256.0f) - mu * mu + 1e-5f);
#pragma unroll
        for (int u = 0; u < 8; u++) {
            int d = lane + 32 * u;
            ss[w * 256 + d] = (vv[u] - mu) * rsd * slot_g[d] + slot_b[d];
        }
    }
    __syncthreads();
    float acc[8];
#pragma unroll
    for (int i = 0; i < 8; i++) acc[i] = 0.f;
    for (int k = 0; k < 256; k++) {
        float wv = q_w[k * 256 + tid];
#pragma unroll
        for (int i = 0; i < 8; i++) acc[i] += ss[i * 256 + k] * wv;
    }
    float qb = q_b[tid];
#pragma unroll
    for (int i = 0; i < 8; i++)
        g_q[(b * 8 + i) * 256 + tid] = (acc[i] + qb) * 0.0625f;  // * D^-0.5
}

// ---------------- per-iter: streaming attention (pipelined, softmax over slots) --------
#define CH 16
#define KVST 264
#define STG_FLOATS (2 * CH * KVST)  // 8448: k-tile then v-tile per stage
#define ATTN_SM_FLOATS (3 * STG_FLOATS + 8 * KVST + CH * 9)  // 27600

__global__ void __launch_bounds__(256) k_attn() {
    extern __shared__ float sm[];
    float* qs = sm + 3 * STG_FLOATS;  // 8 x 264 (h-split layout)
    float* dt = qs + 8 * KVST;        // 16 x 9
    int tile = blockIdx.x, b = blockIdx.y;
    int tid = threadIdx.x;
    uint32_t smbase = (uint32_t)__cvta_generic_to_shared(sm);

    // stage q with h-split map (float f -> f + (f>=128 ? 4 : 0))
    for (int i = tid; i < 2048; i += 256) {
        int s = i >> 8, f = i & 255;
        qs[s * KVST + f + ((f >= 128) ? 4 : 0)] = g_q[b * 2048 + i];
    }

    int tb0 = tile * 128;
    int r = tid >> 4, j = tid & 15;

    auto stage = [&](int c) {
        unsigned st = ((unsigned)c) % 3u;
        const float* krow = g_k + ((size_t)(b * 4096 + tb0 + c * CH + r)) * 256;
        const float* vrow = g_v + ((size_t)(b * 4096 + tb0 + c * CH + r)) * 256;
        uint32_t kdst = smbase + (st * STG_FLOATS + r * KVST) * 4;
        uint32_t vdst = kdst + CH * KVST * 4;
#pragma unroll
        for (int q2 = 0; q2 < 4; q2++) {
            int f = (j * 4 + q2) * 4;
            uint32_t off = (uint32_t)((f + ((f >= 128) ? 4 : 0)) * 4);
            asm volatile("cp.async.cg.shared.global [%0], [%1], 16;" ::"r"(kdst + off),
                         "l"(krow + f));
            asm volatile("cp.async.cg.shared.global [%0], [%1], 16;" ::"r"(vdst + off),
                         "l"(vrow + f));
        }
        asm volatile("cp.async.commit_group;");
    };
    stage(0);
    stage(1);

    int t_d = tid >> 4, s_d = (tid >> 1) & 7, h_d = tid & 1;
    int s_v = tid >> 5, dc = tid & 31;
    int of0 = dc * 4;        // d = dc*4 .. +3
    int of1 = 132 + dc * 4;  // d = 128 + dc*4 .. +3
    float av[8];
#pragma unroll
    for (int i2 = 0; i2 < 8; i2++) av[i2] = 0.f;
    float psreg = 0.f;

    for (int c = 0; c < 8; c++) {
        asm volatile("cp.async.wait_group 1;");
        __syncthreads();
        if (c + 2 < 8) stage(c + 2);
        else asm volatile("cp.async.commit_group;");
        const float* kb = sm + (((unsigned)c) % 3u) * STG_FLOATS;
        const float* vb = kb + CH * KVST;
        // dots: thread = (token, slot, half)
        {
            const float* krow2 = kb + t_d * KVST + h_d * 132;
            const float* qrow = qs + s_d * KVST + h_d * 132;
            float p = 0.f;
#pragma unroll
            for (int kk = 0; kk < 128; kk += 4) {
                float4 kv4 = *(const float4*)(krow2 + kk);
                float4 qv4 = *(const float4*)(qrow + kk);
                p += kv4.x * qv4.x + kv4.y * qv4.y + kv4.z * qv4.z + kv4.w * qv4.w;
            }
            p += __shfl_xor_sync(0xffffffffu, p, 1);
            if (h_d == 0) dt[t_d * 9 + s_d] = p;
        }
        __syncthreads();
        // softmax over slots, per token
        if (tid < CH) {
            float e[8], m = -1e30f;
#pragma unroll
            for (int s = 0; s < 8; s++) {
                e[s] = dt[tid * 9 + s];
                m = fmaxf(m, e[s]);
            }
            float tot = 0.f;
#pragma unroll
            for (int s = 0; s < 8; s++) {
                e[s] = __expf(e[s] - m);
                tot += e[s];
            }
            float inv = 1.f / tot;
#pragma unroll
            for (int s = 0; s < 8; s++) dt[tid * 9 + s] = e[s] * inv + 1e-8f;
        }
        __syncthreads();
        if (tid < 8) {
#pragma unroll
            for (int t = 0; t < CH; t++) psreg += dt[t * 9 + tid];
        }
        // v accumulate: thread = (slot, d-chunk)
#pragma unroll 4
        for (int t = 0; t < CH; t++) {
            float a = dt[t * 9 + s_v];
            float4 v0 = *(const float4*)(vb + t * KVST + of0);
            float4 v1 = *(const float4*)(vb + t * KVST + of1);
            av[0] += a * v0.x; av[1] += a * v0.y; av[2] += a * v0.z; av[3] += a * v0.w;
            av[4] += a * v1.x; av[5] += a * v1.y; av[6] += a * v1.z; av[7] += a * v1.w;
        }
    }
    size_t obase = ((size_t)(b * 32 + tile)) * 2048 + s_v * 256;
    *(float4*)&g_upd_part[obase + dc * 4] = make_float4(av[0], av[1], av[2], av[3]);
    *(float4*)&g_upd_part[obase + 128 + dc * 4] = make_float4(av[4], av[5], av[6], av[7]);
    if (tid < 8) g_psum_part[(b * 32 + tile) * 8 + tid] = psreg;
}

// ---------------- per-iter: finalize upd (deterministic fixed-order reduce) ----------------
__global__ void __launch_bounds__(256) k_upd() {
    int b = blockIdx.x, tid = threadIdx.x;
    __shared__ float ps[8];
    if (tid < 8) {
        float s = 0.f;
        for (int tl = 0; tl < 32; tl++) s += g_psum_part[(b * 32 + tl) * 8 + tid];
        ps[tid] = s;
    }
    __syncthreads();
#pragma unroll
    for (int i = 0; i < 8; i++) {
        float s = 0.f;
        for (int tl = 0; tl < 32; tl++)
            s += g_upd_part[((size_t)(b * 32 + tl)) * 2048 + i * 256 + tid];
        g_upd[b * 2048 + i * 256 + tid] = s / ps[i];
    }
}

// ---------------- per-iter: GRU gate GEMMs (split over 3 blocks per batch) ----------------
__global__ void __launch_bounds__(256) k_gates(const float* __restrict__ wih,
                                               const float* __restrict__ whh,
                                               const float* __restrict__ bih,
                                               const float* __restrict__ bhh) {
    __shared__ float u[2048], pv[2048];
    int b = blockIdx.x, cc = blockIdx.y, tid = threadIdx.x;
    for (int i = tid; i < 2048; i += 256) {
        u[i] = g_upd[b * 2048 + i];
        pv[i] = g_slots[b * 2048 + i];
    }
    __syncthreads();
    int c = cc * 256 + tid;
    float aI[8], aH[8];
    float bi = bih[c], bh = bhh[c];
#pragma unroll
    for (int s = 0; s < 8; s++) { aI[s] = bi; aH[s] = bh; }
    for (int k = 0; k < 256; k++) {
        float wi = wih[k * 768 + c], wh = whh[k * 768 + c];
#pragma unroll
        for (int s = 0; s < 8; s++) {
            aI[s] += u[s * 256 + k] * wi;
            aH[s] += pv[s * 256 + k] * wh;
        }
    }
#pragma unroll
    for (int s = 0; s < 8; s++) {
        g_gi[(b * 8 + s) * 768 + c] = aI[s];
        g_gh[(b * 8 + s) * 768 + c] = aH[s];
    }
}

// ---------------- per-iter: GRU pointwise + residual slot MLP ----------------
__global__ void __launch_bounds__(256) k_gru2(
    const float* __restrict__ pre_g, const float* __restrict__ pre_b,
    const float* __restrict__ w1, const float* __restrict__ b1,
    const float* __restrict__ w2, const float* __restrict__ b2) {
    __shared__ float hn[2048], ff[2048], mid[2048];
    int b = blockIdx.x, tid = threadIdx.x;
#pragma unroll
    for (int s = 0; s < 8; s++) {
        size_t gb = (size_t)(b * 8 + s) * 768 + tid;
        float r = 1.f / (1.f + __expf(-(g_gi[gb] + g_gh[gb])));
        float z = 1.f / (1.f + __expf(-(g_gi[gb + 256] + g_gh[gb + 256])));
        float n = tanhf(g_gi[gb + 512] + r * g_gh[gb + 512]);
        hn[s * 256 + tid] = (1.f - z) * n + z * g_slots[b * 2048 + s * 256 + tid];
    }
    __syncthreads();
    {
        int w = tid >> 5, lane = tid & 31;
        float vv[8];
        float s1 = 0.f, s2 = 0.f;
#pragma unroll
        for (int uu = 0; uu < 8; uu++) {
            vv[uu] = hn[w * 256 + lane + 32 * uu];
            s1 += vv[uu];
            s2 += vv[uu] * vv[uu];
        }
        s1 = warp_sum(s1);
        s2 = warp_sum(s2);
        float mu = s1 * (1.0f / 256.0f);
        float rsd = rsqrtf(s2 * (1.0f / 256.0f) - mu * mu + 1e-5f);
#pragma unroll
        for (int uu = 0; uu < 8; uu++) {
            int d = lane + 32 * uu;
            ff[w * 256 + d] = (vv[uu] - mu) * rsd * pre_g[d] + pre_b[d];
        }
    }
    __syncthreads();
    {
        float acc[8];
        float bb = b1[tid];
#pragma unroll
        for (int s = 0; s < 8; s++) acc[s] = bb;
        for (int k = 0; k < 256; k++) {
            float wv = w1[k * 256 + tid];
#pragma unroll
            for (int s = 0; s < 8; s++) acc[s] += ff[s * 256 + k] * wv;
        }
#pragma unroll
        for (int s = 0; s < 8; s++) mid[s * 256 + tid] = fmaxf(acc[s], 0.f);
    }
    __syncthreads();
    {
        float acc[8];
        float bb = b2[tid];
#pragma unroll
        for (int s = 0; s < 8; s++) acc[s] = bb;
        for (int k = 0; k < 256; k++) {
            float wv = w2[k * 256 + tid];
#pragma unroll
            for (int s = 0; s < 8; s++) acc[s] += mid[s * 256 + k] * wv;
        }
#pragma unroll
        for (int s = 0; s < 8; s++)
            g_slots[b * 2048 + s * 256 + tid] = hn[s * 256 + tid] + fmaxf(acc[s], 0.f);
    }
}

__global__ void k_copy(float* __restrict__ out) {
    int i = blockIdx.x * 256 + threadIdx.x;
    if (i < NB * NSLOT * ND) out[i] = g_slots[i];
}

// ---------------- host launcher ----------------
extern "C" void kernel_launch(void* const* d_in, const int* in_sizes, int n_in,
                              void* d_out, int out_size) {
    const float* x          = (const float*)d_in[0];
    const float* eps_noise  = (const float*)d_in[1];
    const float* pos_w      = (const float*)d_in[2];
    const float* pos_b      = (const float*)d_in[3];
    const float* enc_g      = (const float*)d_in[4];
    const float* enc_b      = (const float*)d_in[5];
    const float* fm_w1      = (const float*)d_in[6];
    const float* fm_b1      = (const float*)d_in[7];
    const float* fm_w2      = (const float*)d_in[8];
    const float* fm_b2      = (const float*)d_in[9];
    const float* in_g       = (const float*)d_in[10];
    const float* in_b       = (const float*)d_in[11];
    const float* q_w        = (const float*)d_in[12];
    const float* q_b        = (const float*)d_in[13];
    const float* k_w        = (const float*)d_in[14];
    const float* k_b        = (const float*)d_in[15];
    const float* v_w        = (const float*)d_in[16];
    const float* v_b        = (const float*)d_in[17];
    const float* gru_wih    = (const float*)d_in[18];
    const float* gru_whh    = (const float*)d_in[19];
    const float* gru_bih    = (const float*)d_in[20];
    const float* gru_bhh    = (const float*)d_in[21];
    const float* pre_g      = (const float*)d_in[22];
    const float* pre_b      = (const float*)d_in[23];
    const float* st_w1      = (const float*)d_in[24];
    const float* st_b1      = (const float*)d_in[25];
    const float* st_w2      = (const float*)d_in[26];
    const float* st_b2      = (const float*)d_in[27];
    const float* slot_g     = (const float*)d_in[28];
    const float* slot_b     = (const float*)d_in[29];
    const float* slots_loc  = (const float*)d_in[30];
    const float* slots_lsc  = (const float*)d_in[31];

    const int ENC_SMEM  = (A_FLOATS + WBUF_FLOATS + 1024 + 256) * 4;  // ~206KB
    const int ATTN_SMEM = ATTN_SM_FLOATS * 4;                         // 110400

    cudaFuncSetAttribute(k_encoder, cudaFuncAttributeMaxDynamicSharedMemorySize, ENC_SMEM);
    cudaFuncSetAttribute(k_attn, cudaFuncAttributeMaxDynamicSharedMemorySize, ATTN_SMEM);

    k_stats<<<dim3(32, 64), 256>>>(x, pos_w, pos_b);
    k_cvtW<<<256, 256>>>(fm_w1, fm_w2, k_w, v_w);
    k_stats2<<<1, 32>>>();
    k_encoder<<<dim3(32, 32), 256, ENC_SMEM>>>(x, pos_w, pos_b, enc_g, enc_b, fm_b1, fm_b2,
                                               in_g, in_b, k_b, v_b);
    k_init<<<32, 256>>>(eps_noise, slots_loc, slots_lsc);
    for (int it = 0; it < 3; it++) {
        k_q<<<32, 256>>>(q_w, q_b, slot_g, slot_b);
        k_attn<<<dim3(32, 32), 256, ATTN_SMEM>>>();
        k_upd<<<32, 256>>>();
        k_gates<<<dim3(32, 3), 256>>>(gru_wih, gru_whh, gru_bih, gru_bhh);
        k_gru2<<<32, 256>>>(pre_g, pre_b, st_w1, st_b1, st_w2, st_b2);
    }
    k_copy<<<256, 256>>>((float*)d_out);
}

// round 8
// speedup vs baseline: 3.3153x; 1.3060x over previous
#include <cuda_runtime.h>
#include <cuda_bf16.h>
#include <math.h>
#include <stdint.h>

#define NB 32
#define ND 256
#define NTOK 4096
#define NSLOT 8

// ---------------- scratch (device globals; no allocation allowed) ----------------
__device__ uint32_t g_kb[NB * NTOK * 128];     // bf16-pair packed k: 67 MB
__device__ uint32_t g_vb[NB * NTOK * 128];     // bf16-pair packed v: 67 MB
__device__ uint32_t g_wp[4][128 * ND];         // bf16-pair packed weights: w1,w2,k,v
__device__ float g_egT[ND * NTOK];             // transposed enc_g [d][tok]
__device__ float g_ebT[ND * NTOK];             // transposed enc_b [d][tok]
__device__ float g_stats_part[NB * 64 * 2];
__device__ float g_stats[NB * 2];              // mean, rstd per batch
__device__ float g_slots[NB * NSLOT * ND];
__device__ float g_q[NB * NSLOT * ND];
__device__ float g_upd_part[NB * 32 * NSLOT * ND];
__device__ float g_psum_part[NB * 32 * NSLOT];
__device__ float g_upd[NB * NSLOT * ND];
__device__ float g_gi[NB * NSLOT * 768];
__device__ float g_gh[NB * NSLOT * 768];

__device__ __forceinline__ float warp_sum(float v) {
#pragma unroll
    for (int o = 16; o; o >>= 1) v += __shfl_xor_sync(0xffffffffu, v, o);
    return v;
}

__device__ __forceinline__ uint32_t packbf(float a, float b) {
    __nv_bfloat162 h = __floats2bfloat162_rn(a, b);  // .x = a (low), .y = b (high)
    return *(uint32_t*)&h;
}
__device__ __forceinline__ float2 unpackbf(uint32_t u) {
    __nv_bfloat162 h = *(__nv_bfloat162*)&u;
    return __bfloat1622float2(h);
}

// ---------------- K0: per-batch sum / sumsq of h = x + pos (exact fp32) ----------------
__global__ void __launch_bounds__(256) k_stats(const float* __restrict__ x,
                                               const float* __restrict__ pos_w,
                                               const float* __restrict__ pos_b) {
    int b = blockIdx.x, c = blockIdx.y, tid = threadIdx.x;
    float s = 0.f, q = 0.f;
    int base = c * 16384;
    for (int e = base + tid; e < base + 16384; e += 256) {
        int d = e >> 12;
        int ij = e & 4095;
        int ti = ij >> 6, tj = ij & 63;
        float fi = ti * (1.0f / 63.0f), fj = tj * (1.0f / 63.0f);
        float p = fi * pos_w[d] + fj * pos_w[256 + d] + (1.0f - fi) * pos_w[512 + d] +
                  (1.0f - fj) * pos_w[768 + d] + pos_b[d];
        float v = x[b * 1048576 + e] + p;
        s += v;
        q += v * v;
    }
    s = warp_sum(s);
    q = warp_sum(q);
    __shared__ float rs[8], rq[8];
    int w = tid >> 5, lane = tid & 31;
    if (lane == 0) { rs[w] = s; rq[w] = q; }
    __syncthreads();
    if (tid == 0) {
        float S = 0.f, Q = 0.f;
#pragma unroll
        for (int i = 0; i < 8; i++) { S += rs[i]; Q += rq[i]; }
        g_stats_part[(b * 64 + c) * 2 + 0] = S;
        g_stats_part[(b * 64 + c) * 2 + 1] = Q;
    }
}

__global__ void k_stats2() {
    int b = threadIdx.x;
    if (b < NB) {
        double S = 0.0, Q = 0.0;
        for (int c = 0; c < 64; c++) {
            S += (double)g_stats_part[(b * 64 + c) * 2 + 0];
            Q += (double)g_stats_part[(b * 64 + c) * 2 + 1];
        }
        double N = 1048576.0;
        double mu = S / N;
        double var = Q / N - mu * mu;
        g_stats[b * 2 + 0] = (float)mu;
        g_stats[b * 2 + 1] = (float)(1.0 / sqrt(var + 1e-5));
    }
}

// ---------------- weight pre-pack to bf16 pairs ----------------
__global__ void __launch_bounds__(256) k_cvtW(const float* __restrict__ w1,
                                              const float* __restrict__ w2,
                                              const float* __restrict__ wk,
                                              const float* __restrict__ wv) {
    int i = blockIdx.x * 256 + threadIdx.x;   // 0 .. 128*256-1
    int kp = i >> 8, c = i & 255;
    const float* srcs[4] = {w1, w2, wk, wv};
#pragma unroll
    for (int m = 0; m < 4; m++) {
        const float* w = srcs[m];
        g_wp[m][i] = packbf(w[(2 * kp) * 256 + c], w[(2 * kp + 1) * 256 + c]);
    }
}

// ---------------- transpose enc_g / enc_b into [d][tok] ----------------
__global__ void __launch_bounds__(256) k_prep(const float* __restrict__ eg,
                                              const float* __restrict__ eb) {
    __shared__ float tile[32][33];
    const float* src = blockIdx.z ? eb : eg;
    float* dst = blockIdx.z ? g_ebT : g_egT;
    int tok0 = blockIdx.x * 32, d0 = blockIdx.y * 32;
    int tx = threadIdx.x & 31, ty = threadIdx.x >> 5;  // 32 x 8
#pragma unroll
    for (int i = 0; i < 4; i++)
        tile[ty + 8 * i][tx] = src[(tok0 + ty + 8 * i) * 256 + d0 + tx];
    __syncthreads();
#pragma unroll
    for (int i = 0; i < 4; i++)
        dst[(d0 + ty + 8 * i) * 4096 + tok0 + tx] = tile[tx][ty + 8 * i];
}

// ---------------- bf16 mma ----------------
__device__ __forceinline__ void mma16bf(float* c, const uint32_t a[4], uint32_t b0,
                                        uint32_t b1) {
    asm volatile(
        "mma.sync.aligned.m16n8k16.row.col.f32.bf16.bf16.f32 "
        "{%0,%1,%2,%3}, {%4,%5,%6,%7}, {%8,%9}, {%0,%1,%2,%3};"
        : "+f"(c[0]), "+f"(c[1]), "+f"(c[2]), "+f"(c[3])
        : "r"(a[0]), "r"(a[1]), "r"(a[2]), "r"(a[3]), "r"(b0), "r"(b1));
}

#define A_ST 132        // A smem row stride (uint32 pairs)
#define W_ST 264        // W chunk smem row stride (uint32)
#define A_U32 (128 * A_ST)
#define WBUF_U32 (4 * 8 * W_ST)   // 4-stage, 8 pair-rows per k16 chunk

// 128x256x256 bf16 GEMM: A (smem pairs) @ W (global pairs) -> acc. 16 warps, 32x64 tiles.
__device__ __forceinline__ void run_gemm(const uint32_t* __restrict__ Wg,
                                         const uint32_t* As, uint32_t* Wbuf,
                                         float acc[2][8][4], int wm, int wn,
                                         int lane, int tid) {
#pragma unroll
    for (int mt = 0; mt < 2; mt++)
#pragma unroll
        for (int nt = 0; nt < 8; nt++)
#pragma unroll
            for (int e = 0; e < 4; e++) acc[mt][nt][e] = 0.f;

    int g = lane >> 2, t = lane & 3;
    uint32_t wb_base = (uint32_t)__cvta_generic_to_shared(Wbuf);

    auto stage = [&](int kc) {
        int st = kc & 3;
        int row = tid >> 6, c4 = (tid & 63) * 4;   // 512 threads, 1 granule each
        uint32_t dst = wb_base + (uint32_t)(((st * 8 + row) * W_ST + c4) * 4);
        const uint32_t* src = Wg + (kc * 8 + row) * 256 + c4;
        asm volatile("cp.async.cg.shared.global [%0], [%1], 16;" ::"r"(dst), "l"(src));
        asm volatile("cp.async.commit_group;");
    };
    stage(0);
    stage(1);
    stage(2);

#pragma unroll 2
    for (int kc = 0; kc < 16; kc++) {
        asm volatile("cp.async.wait_group 2;");
        __syncthreads();
        if (kc + 3 < 16) stage(kc + 3);
        else asm volatile("cp.async.commit_group;");
        const uint32_t* Wb = Wbuf + (kc & 3) * 8 * W_ST;
        int k0p = kc * 8;
        uint32_t a[2][4];
#pragma unroll
        for (int mt = 0; mt < 2; mt++) {
            int r = wm * 32 + mt * 16 + g;
            a[mt][0] = As[r * A_ST + k0p + t];
            a[mt][1] = As[(r + 8) * A_ST + k0p + t];
            a[mt][2] = As[r * A_ST + k0p + t + 4];
            a[mt][3] = As[(r + 8) * A_ST + k0p + t + 4];
        }
#pragma unroll
        for (int nt = 0; nt < 8; nt++) {
            int c = wn * 64 + nt * 8 + g;
            uint32_t b0 = Wb[t * W_ST + c];
            uint32_t b1 = Wb[(t + 4) * W_ST + c];
            mma16bf(acc[0][nt], a[0], b0, b1);
            mma16bf(acc[1][nt], a[1], b0, b1);
        }
    }
    __syncthreads();
}

// ---------------- K1: fused bf16 tensor-core encoder (512 threads) ----------------
__global__ void __launch_bounds__(512, 1) k_encoder(
    const float* __restrict__ x, const float* __restrict__ pos_w,
    const float* __restrict__ pos_b, const float* __restrict__ fm_b1,
    const float* __restrict__ fm_b2, const float* __restrict__ in_g,
    const float* __restrict__ in_b, const float* __restrict__ k_b,
    const float* __restrict__ v_b) {
    extern __shared__ char smraw[];
    uint32_t* A = (uint32_t*)smraw;               // 128*132 u32
    uint32_t* Wbuf = A + A_U32;                   // 4*8*264 u32
    float* pw = (float*)(Wbuf + WBUF_U32);        // 1024
    float* pb = pw + 1024;                        // 256

    int b = blockIdx.y;
    int t0 = blockIdx.x * 128;
    int tid = threadIdx.x;
    int wid = tid >> 5, lane = tid & 31;
    int wm = wid & 3, wn = wid >> 2;              // 4 x 4 warp grid, tile 32x64
    int g = lane >> 2, t = lane & 3;

    for (int i = tid; i < 1024; i += 512) pw[i] = pos_w[i];
    if (tid < 256) pb[tid] = pos_b[tid];
    float mean = g_stats[b * 2 + 0], rstd = g_stats[b * 2 + 1];
    __syncthreads();

    // fused load: x + pos -> global LN -> enc_g/enc_b -> bf16 pack into A
    // 512 threads, 4 per row, 32 pairs each (FULL 128-pair coverage)
    {
        int r2 = tid >> 2, qq = tid & 3;
        int tok = t0 + r2;
        int ti = tok >> 6, tj = tok & 63;
        float fi = ti * (1.0f / 63.0f), fj = tj * (1.0f / 63.0f);
#pragma unroll 4
        for (int i = 0; i < 32; i++) {
            int p = qq * 32 + i;
            int d0 = 2 * p, d1 = d0 + 1;
            float p0 = fi * pw[d0] + fj * pw[256 + d0] + (1.0f - fi) * pw[512 + d0] +
                       (1.0f - fj) * pw[768 + d0] + pb[d0];
            float p1 = fi * pw[d1] + fj * pw[256 + d1] + (1.0f - fi) * pw[512 + d1] +
                       (1.0f - fj) * pw[768 + d1] + pb[d1];
            float x0 = x[(b * 256 + d0) * 4096 + tok];
            float x1 = x[(b * 256 + d1) * 4096 + tok];
            float e0 = g_egT[d0 * 4096 + tok], e1 = g_egT[d1 * 4096 + tok];
            float c0 = g_ebT[d0 * 4096 + tok], c1 = g_ebT[d1 * 4096 + tok];
            float v0 = (x0 + p0 - mean) * rstd * e0 + c0;
            float v1 = (x1 + p1 - mean) * rstd * e1 + c1;
            A[r2 * A_ST + p] = packbf(v0, v1);
        }
    }
    __syncthreads();

    float acc[2][8][4];

    // GEMM1 + relu -> A
    run_gemm(g_wp[0], A, Wbuf, acc, wm, wn, lane, tid);
#pragma unroll
    for (int nt = 0; nt < 8; nt++) {
        int c = wn * 64 + nt * 8 + 2 * t;
        int p = c >> 1;
        float2 bb = *(const float2*)&fm_b1[c];
#pragma unroll
        for (int mt = 0; mt < 2; mt++) {
            int r = wm * 32 + mt * 16 + g;
            float* a = acc[mt][nt];
            A[r * A_ST + p] = packbf(fmaxf(a[0] + bb.x, 0.f), fmaxf(a[1] + bb.y, 0.f));
            A[(r + 8) * A_ST + p] =
                packbf(fmaxf(a[2] + bb.x, 0.f), fmaxf(a[3] + bb.y, 0.f));
        }
    }
    __syncthreads();

    // GEMM2 + relu -> A
    run_gemm(g_wp[1], A, Wbuf, acc, wm, wn, lane, tid);
#pragma unroll
    for (int nt = 0; nt < 8; nt++) {
        int c = wn * 64 + nt * 8 + 2 * t;
        int p = c >> 1;
        float2 bb = *(const float2*)&fm_b2[c];
#pragma unroll
        for (int mt = 0; mt < 2; mt++) {
            int r = wm * 32 + mt * 16 + g;
            float* a = acc[mt][nt];
            A[r * A_ST + p] = packbf(fmaxf(a[0] + bb.x, 0.f), fmaxf(a[1] + bb.y, 0.f));
            A[(r + 8) * A_ST + p] =
                packbf(fmaxf(a[2] + bb.x, 0.f), fmaxf(a[3] + bb.y, 0.f));
        }
    }
    __syncthreads();

    // per-token LayerNorm over D (16 warps x 8 rows)
    for (int rr = 0; rr < 8; rr++) {
        int r = wid * 8 + rr;
        float2 vv[4];
        float s1 = 0.f, s2 = 0.f;
#pragma unroll
        for (int u = 0; u < 4; u++) {
            vv[u] = unpackbf(A[r * A_ST + lane + 32 * u]);
            s1 += vv[u].x + vv[u].y;
            s2 += vv[u].x * vv[u].x + vv[u].y * vv[u].y;
        }
        s1 = warp_sum(s1);
        s2 = warp_sum(s2);
        float mu = s1 * (1.0f / 256.0f);
        float rsd = rsqrtf(s2 * (1.0f / 256.0f) - mu * mu + 1e-5f);
#pragma unroll
        for (int u = 0; u < 4; u++) {
            int p = lane + 32 * u;
            float2 ig = *(const float2*)&in_g[2 * p];
            float2 ib = *(const float2*)&in_b[2 * p];
            A[r * A_ST + p] = packbf((vv[u].x - mu) * rsd * ig.x + ib.x,
                                     (vv[u].y - mu) * rsd * ig.y + ib.y);
        }
    }
    __syncthreads();

    // k projection -> g_kb (bf16 pairs)
    run_gemm(g_wp[2], A, Wbuf, acc, wm, wn, lane, tid);
#pragma unroll
    for (int nt = 0; nt < 8; nt++) {
        int c = wn * 64 + nt * 8 + 2 * t;
        int p = c >> 1;
        float2 bb = *(const float2*)&k_b[c];
#pragma unroll
        for (int mt = 0; mt < 2; mt++) {
            int r = wm * 32 + mt * 16 + g;
            float* a = acc[mt][nt];
            g_kb[((size_t)(b * 4096 + t0 + r)) * 128 + p] =
                packbf(a[0] + bb.x, a[1] + bb.y);
            g_kb[((size_t)(b * 4096 + t0 + r + 8)) * 128 + p] =
                packbf(a[2] + bb.x, a[3] + bb.y);
        }
    }

    // v projection -> g_vb (bf16 pairs)
    run_gemm(g_wp[3], A, Wbuf, acc, wm, wn, lane, tid);
#pragma unroll
    for (int nt = 0; nt < 8; nt++) {
        int c = wn * 64 + nt * 8 + 2 * t;
        int p = c >> 1;
        float2 bb = *(const float2*)&v_b[c];
#pragma unroll
        for (int mt = 0; mt < 2; mt++) {
            int r = wm * 32 + mt * 16 + g;
            float* a = acc[mt][nt];
            g_vb[((size_t)(b * 4096 + t0 + r)) * 128 + p] =
                packbf(a[0] + bb.x, a[1] + bb.y);
            g_vb[((size_t)(b * 4096 + t0 + r + 8)) * 128 + p] =
                packbf(a[2] + bb.x, a[3] + bb.y);
        }
    }
}

// ---------------- slot init ----------------
__global__ void k_init(const float* __restrict__ eps, const float* __restrict__ loc,
                       const float* __restrict__ lsc) {
    int b = blockIdx.x, tid = threadIdx.x;
    for (int idx = tid; idx < 2048; idx += 256) {
        int d = idx & 255;
        g_slots[b * 2048 + idx] = loc[d] + __expf(lsc[d]) * eps[b * 2048 + idx];
    }
}

// ---------------- per-iter: slot LN + q projection (scaled, fp32) ----------------
__global__ void __launch_bounds__(256) k_q(const float* __restrict__ q_w,
                                           const float* __restrict__ q_b,
                                           const float* __restrict__ slot_g,
                                           const float* __restrict__ slot_b) {
    __shared__ float ss[8 * 256];
    int b = blockIdx.x, tid = threadIdx.x, w = tid >> 5, lane = tid & 31;
    {
        float vv[8];
        float s1 = 0.f, s2 = 0.f;
#pragma unroll
        for (int u = 0; u < 8; u++) {
            vv[u] = g_slots[(b * 8 + w) * 256 + lane + 32 * u];
            s1 += vv[u];
            s2 += vv[u] * vv[u];
        }
        s1 = warp_sum(s1);
        s2 = warp_sum(s2);
        float mu = s1 * (1.0f / 256.0f);
        float rsd = rsqrtf(s2 * (1.0f / 256.0f) - mu * mu + 1e-5f);
#pragma unroll
        for (int u = 0; u < 8; u++) {
            int d = lane + 32 * u;
            ss[w * 256 + d] = (vv[u] - mu) * rsd * slot_g[d] + slot_b[d];
        }
    }
    __syncthreads();
    float acc[8];
#pragma unroll
    for (int i = 0; i < 8; i++) acc[i] = 0.f;
    for (int k = 0; k < 256; k++) {
        float wv = q_w[k * 256 + tid];
#pragma unroll
        for (int i = 0; i < 8; i++) acc[i] += ss[i * 256 + k] * wv;
    }
    float qb = q_b[tid];
#pragma unroll
    for (int i = 0; i < 8; i++)
        g_q[(b * 8 + i) * 256 + tid] = (acc[i] + qb) * 0.0625f;  // * D^-0.5
}

// ---------------- per-iter: streaming attention (bf16 k/v, pipelined) ----------------
#define CH 16
#define KVSTu 136                       // u32 per row, halves at 0 / 68
#define STG_U32 (2 * CH * KVSTu)        // 4352: k then v
#define QST 264                         // floats, halves at 0 / 132
#define ATTN_SMEM_BYTES (3 * STG_U32 * 4 + (8 * QST + CH * 9) * 4)

__global__ void __launch_bounds__(256) k_attn() {
    extern __shared__ char smraw[];
    uint32_t* stg = (uint32_t*)smraw;
    float* qs = (float*)(stg + 3 * STG_U32);
    float* dt = qs + 8 * QST;
    int tile = blockIdx.x, b = blockIdx.y;
    int tid = threadIdx.x;
    uint32_t smbase = (uint32_t)__cvta_generic_to_shared(stg);

    // stage q with h-split (float f -> +4 if f>=128)
    for (int i = tid; i < 2048; i += 256) {
        int s = i >> 8, f = i & 255;
        qs[s * QST + f + ((f >= 128) ? 4 : 0)] = g_q[b * 2048 + i];
    }

    int tb0 = tile * 128;

    auto stage = [&](int c) {
        unsigned st = ((unsigned)c) % 3u;
        uint32_t sb = smbase + st * STG_U32 * 4;
#pragma unroll
        for (int e = 0; e < 2; e++) {
            int gidx = tid * 2 + e;                 // 0..511
            int row = gidx >> 5, g32 = gidx & 31;   // 32 granules/row
            uint32_t off = (uint32_t)((g32 * 4 + ((g32 >= 16) ? 4 : 0)) * 4);
            size_t gsrc = ((size_t)(b * 4096 + tb0 + c * CH + row)) * 128 + g32 * 4;
            uint32_t kdst = sb + (uint32_t)(row * KVSTu * 4) + off;
            asm volatile("cp.async.cg.shared.global [%0], [%1], 16;" ::"r"(kdst),
                         "l"(g_kb + gsrc));
            asm volatile("cp.async.cg.shared.global [%0], [%1], 16;" ::"r"(
                             kdst + CH * KVSTu * 4),
                         "l"(g_vb + gsrc));
        }
        asm volatile("cp.async.commit_group;");
    };
    stage(0);
    stage(1);

    int t_d = tid >> 4, s_d = (tid >> 1) & 7, h_d = tid & 1;
    int s_v = tid >> 5, dc = tid & 31;
    uint32_t voff = dc * 4 + ((dc >= 16) ? 4 : 0);
    float av[8];
#pragma unroll
    for (int i2 = 0; i2 < 8; i2++) av[i2] = 0.f;
    float psreg = 0.f;

    for (int c = 0; c < 8; c++) {
        asm volatile("cp.async.wait_group 1;");
        __syncthreads();
        if (c + 2 < 8) stage(c + 2);
        else asm volatile("cp.async.commit_group;");
        const uint32_t* kb = stg + (((unsigned)c) % 3u) * STG_U32;
        const uint32_t* vb = kb + CH * KVSTu;
        // dots: thread = (token, slot, half)
        {
            const uint32_t* krow = kb + t_d * KVSTu + h_d * 68;
            const float* qrow = qs + s_d * QST + h_d * 132;
            float p = 0.f;
#pragma unroll
            for (int i = 0; i < 16; i++) {
                uint4 kq = *(const uint4*)(krow + i * 4);
                float4 q0 = *(const float4*)(qrow + i * 8);
                float4 q1 = *(const float4*)(qrow + i * 8 + 4);
                float2 f0 = unpackbf(kq.x), f1 = unpackbf(kq.y);
                float2 f2 = unpackbf(kq.z), f3 = unpackbf(kq.w);
                p += f0.x * q0.x + f0.y * q0.y + f1.x * q0.z + f1.y * q0.w;
                p += f2.x * q1.x + f2.y * q1.y + f3.x * q1.z + f3.y * q1.w;
            }
            p += __shfl_xor_sync(0xffffffffu, p, 1);
            if (h_d == 0) dt[t_d * 9 + s_d] = p;
        }
        __syncthreads();
        // softmax over slots, per token
        if (tid < CH) {
            float e[8], m = -1e30f;
#pragma unroll
            for (int s = 0; s < 8; s++) {
                e[s] = dt[tid * 9 + s];
                m = fmaxf(m, e[s]);
            }
            float tot = 0.f;
#pragma unroll
            for (int s = 0; s < 8; s++) {
                e[s] = __expf(e[s] - m);
                tot += e[s];
            }
            float inv = 1.f / tot;
#pragma unroll
            for (int s = 0; s < 8; s++) dt[tid * 9 + s] = e[s] * inv + 1e-8f;
        }
        __syncthreads();
        if (tid < 8) {
#pragma unroll
            for (int t = 0; t < CH; t++) psreg += dt[t * 9 + tid];
        }
        // v accumulate: thread = (slot, d-chunk of 8)
#pragma unroll 4
        for (int t = 0; t < CH; t++) {
            float a = dt[t * 9 + s_v];
            uint4 vq = *(const uint4*)(vb + t * KVSTu + voff);
            float2 f0 = unpackbf(vq.x), f1 = unpackbf(vq.y);
            float2 f2 = unpackbf(vq.z), f3 = unpackbf(vq.w);
            av[0] += a * f0.x; av[1] += a * f0.y;
            av[2] += a * f1.x; av[3] += a * f1.y;
            av[4] += a * f2.x; av[5] += a * f2.y;
            av[6] += a * f3.x; av[7] += a * f3.y;
        }
    }
    size_t obase = ((size_t)(b * 32 + tile)) * 2048 + s_v * 256 + dc * 8;
    *(float4*)&g_upd_part[obase] = make_float4(av[0], av[1], av[2], av[3]);
    *(float4*)&g_upd_part[obase + 4] = make_float4(av[4], av[5], av[6], av[7]);
    if (tid < 8) g_psum_part[(b * 32 + tile) * 8 + tid] = psreg;
}

// ---------------- per-iter: finalize upd (deterministic fixed-order reduce) ----------------
__global__ void __launch_bounds__(256) k_upd() {
    int b = blockIdx.x, tid = threadIdx.x;
    __shared__ float ps[8];
    if (tid < 8) {
        float s = 0.f;
        for (int tl = 0; tl < 32; tl++) s += g_psum_part[(b * 32 + tl) * 8 + tid];
        ps[tid] = s;
    }
    __syncthreads();
#pragma unroll
    for (int i = 0; i < 8; i++) {
        float s = 0.f;
        for (int tl = 0; tl < 32; tl++)
            s += g_upd_part[((size_t)(b * 32 + tl)) * 2048 + i * 256 + tid];
        g_upd[b * 2048 + i * 256 + tid] = s / ps[i];
    }
}

// ---------------- per-iter: GRU gate GEMMs (3 blocks per batch) ----------------
__global__ void __launch_bounds__(256) k_gates(const float* __restrict__ wih,
                                               const float* __restrict__ whh,
                                               const float* __restrict__ bih,
                                               const float* __restrict__ bhh) {
    __shared__ float u[2048], pv[2048];
    int b = blockIdx.x, cc = blockIdx.y, tid = threadIdx.x;
    for (int i = tid; i < 2048; i += 256) {
        u[i] = g_upd[b * 2048 + i];
        pv[i] = g_slots[b * 2048 + i];
    }
    __syncthreads();
    int c = cc * 256 + tid;
    float aI[8], aH[8];
    float bi = bih[c], bh = bhh[c];
#pragma unroll
    for (int s = 0; s < 8; s++) { aI[s] = bi; aH[s] = bh; }
    for (int k = 0; k < 256; k++) {
        float wi = wih[k * 768 + c], wh = whh[k * 768 + c];
#pragma unroll
        for (int s = 0; s < 8; s++) {
            aI[s] += u[s * 256 + k] * wi;
            aH[s] += pv[s * 256 + k] * wh;
        }
    }
#pragma unroll
    for (int s = 0; s < 8; s++) {
        g_gi[(b * 8 + s) * 768 + c] = aI[s];
        g_gh[(b * 8 + s) * 768 + c] = aH[s];
    }
}

// ---------------- per-iter: GRU pointwise + residual slot MLP ----------------
__global__ void __launch_bounds__(256) k_gru2(
    const float* __restrict__ pre_g, const float* __restrict__ pre_b,
    const float* __restrict__ w1, const float* __restrict__ b1,
    const float* __restrict__ w2, const float* __restrict__ b2) {
    __shared__ float hn[2048], ff[2048], mid[2048];
    int b = blockIdx.x, tid = threadIdx.x;
#pragma unroll
    for (int s = 0; s < 8; s++) {
        size_t gb = (size_t)(b * 8 + s) * 768 + tid;
        float r = 1.f / (1.f + __expf(-(g_gi[gb] + g_gh[gb])));
        float z = 1.f / (1.f + __expf(-(g_gi[gb + 256] + g_gh[gb + 256])));
        float n = tanhf(g_gi[gb + 512] + r * g_gh[gb + 512]);
        hn[s * 256 + tid] = (1.f - z) * n + z * g_slots[b * 2048 + s * 256 + tid];
    }
    __syncthreads();
    {
        int w = tid >> 5, lane = tid & 31;
        float vv[8];
        float s1 = 0.f, s2 = 0.f;
#pragma unroll
        for (int uu = 0; uu < 8; uu++) {
            vv[uu] = hn[w * 256 + lane + 32 * uu];
            s1 += vv[uu];
            s2 += vv[uu] * vv[uu];
        }
        s1 = warp_sum(s1);
        s2 = warp_sum(s2);
        float mu = s1 * (1.0f / 256.0f);
        float rsd = rsqrtf(s2 * (1.0f / 256.0f) - mu * mu + 1e-5f);
#pragma unroll
        for (int uu = 0; uu < 8; uu++) {
            int d = lane + 32 * uu;
            ff[w * 256 + d] = (vv[uu] - mu) * rsd * pre_g[d] + pre_b[d];
        }
    }
    __syncthreads();
    {
        float acc[8];
        float bb = b1[tid];
#pragma unroll
        for (int s = 0; s < 8; s++) acc[s] = bb;
        for (int k = 0; k < 256; k++) {
            float wv = w1[k * 256 + tid];
#pragma unroll
            for (int s = 0; s < 8; s++) acc[s] += ff[s * 256 + k] * wv;
        }
#pragma unroll
        for (int s = 0; s < 8; s++) mid[s * 256 + tid] = fmaxf(acc[s], 0.f);
    }
    __syncthreads();
    {
        float acc[8];
        float bb = b2[tid];
#pragma unroll
        for (int s = 0; s < 8; s++) acc[s] = bb;
        for (int k = 0; k < 256; k++) {
            float wv = w2[k * 256 + tid];
#pragma unroll
            for (int s = 0; s < 8; s++) acc[s] += mid[s * 256 + k] * wv;
        }
#pragma unroll
        for (int s = 0; s < 8; s++)
            g_slots[b * 2048 + s * 256 + tid] = hn[s * 256 + tid] + fmaxf(acc[s], 0.f);
    }
}

__global__ void k_copy(float* __restrict__ out) {
    int i = blockIdx.x * 256 + threadIdx.x;
    if (i < NB * NSLOT * ND) out[i] = g_slots[i];
}

// ---------------- host launcher ----------------
extern "C" void kernel_launch(void* const* d_in, const int* in_sizes, int n_in,
                              void* d_out, int out_size) {
    const float* x          = (const float*)d_in[0];
    const float* eps_noise  = (const float*)d_in[1];
    const float* pos_w      = (const float*)d_in[2];
    const float* pos_b      = (const float*)d_in[3];
    const float* enc_g      = (const float*)d_in[4];
    const float* enc_b      = (const float*)d_in[5];
    const float* fm_w1      = (const float*)d_in[6];
    const float* fm_b1      = (const float*)d_in[7];
    const float* fm_w2      = (const float*)d_in[8];
    const float* fm_b2      = (const float*)d_in[9];
    const float* in_g       = (const float*)d_in[10];
    const float* in_b       = (const float*)d_in[11];
    const float* q_w        = (const float*)d_in[12];
    const float* q_b        = (const float*)d_in[13];
    const float* k_w        = (const float*)d_in[14];
    const float* k_b        = (const float*)d_in[15];
    const float* v_w        = (const float*)d_in[16];
    const float* v_b        = (const float*)d_in[17];
    const float* gru_wih    = (const float*)d_in[18];
    const float* gru_whh    = (const float*)d_in[19];
    const float* gru_bih    = (const float*)d_in[20];
    const float* gru_bhh    = (const float*)d_in[21];
    const float* pre_g      = (const float*)d_in[22];
    const float* pre_b      = (const float*)d_in[23];
    const float* st_w1      = (const float*)d_in[24];
    const float* st_b1      = (const float*)d_in[25];
    const float* st_w2      = (const float*)d_in[26];
    const float* st_b2      = (const float*)d_in[27];
    const float* slot_g     = (const float*)d_in[28];
    const float* slot_b     = (const float*)d_in[29];
    const float* slots_loc  = (const float*)d_in[30];
    const float* slots_lsc  = (const float*)d_in[31];

    const int ENC_SMEM = (A_U32 + WBUF_U32) * 4 + (1024 + 256) * 4;  // 106496
    const int ATTN_SMEM = ATTN_SMEM_BYTES;                           // 61248

    cudaFuncSetAttribute(k_encoder, cudaFuncAttributeMaxDynamicSharedMemorySize, ENC_SMEM);
    cudaFuncSetAttribute(k_attn, cudaFuncAttributeMaxDynamicSharedMemorySize, ATTN_SMEM);

    k_stats<<<dim3(32, 64), 256>>>(x, pos_w, pos_b);
    k_cvtW<<<128, 256>>>(fm_w1, fm_w2, k_w, v_w);
    k_prep<<<dim3(128, 8, 2), 256>>>(enc_g, enc_b);
    k_stats2<<<1, 32>>>();
    k_encoder<<<dim3(32, 32), 512, ENC_SMEM>>>(x, pos_w, pos_b, fm_b1, fm_b2, in_g, in_b,
                                               k_b, v_b);
    k_init<<<32, 256>>>(eps_noise, slots_loc, slots_lsc);
    for (int it = 0; it < 3; it++) {
        k_q<<<32, 256>>>(q_w, q_b, slot_g, slot_b);
        k_attn<<<dim3(32, 32), 256, ATTN_SMEM>>>();
        k_upd<<<32, 256>>>();
        k_gates<<<dim3(32, 3), 256>>>(gru_wih, gru_whh, gru_bih, gru_bhh);
        k_gru2<<<32, 256>>>(pre_g, pre_b, st_w1, st_b1, st_w2, st_b2);
    }
    k_copy<<<256, 256>>>((float*)d_out);
}